// round 11
// baseline (speedup 1.0000x reference)
#include <cuda_runtime.h>
#include <cuda_bf16.h>
#include <cstdint>
#include <math.h>

#define D_MODEL 1024
#define NHEAD   16
#define HD      64
#define SEQ     2048
#define BATCH   4
#define MTOT    (BATCH*SEQ)      // 8192
#define BHN     (BATCH*NHEAD)    // 64

static __device__ __nv_bfloat16 g_xln[MTOT * D_MODEL];
static __device__ __nv_bfloat16 g_q[BHN * SEQ * HD];
static __device__ __nv_bfloat16 g_k[BHN * SEQ * HD];
static __device__ __nv_bfloat16 g_v[BHN * SEQ * HD];
static __device__ __nv_bfloat16 g_ctx[MTOT * D_MODEL];
static __device__ __nv_bfloat16 g_wq[D_MODEL * D_MODEL];
static __device__ __nv_bfloat16 g_wk[D_MODEL * D_MODEL];
static __device__ __nv_bfloat16 g_wv[D_MODEL * D_MODEL];
static __device__ __nv_bfloat16 g_wo[D_MODEL * D_MODEL];
static __device__ float g_emb[SEQ * HD];

// GEMM smem: 3 stages x (A[128] + B[256]) rows of 72 bf16 (144B pitch)
#define G_PITCHB  144
#define G_ASIZE   (128 * G_PITCHB)           // 18432
#define G_BSIZE   (256 * G_PITCHB)           // 36864
#define G_STAGE_BYTES (G_ASIZE + G_BSIZE)    // 55296
#define G_SMEM_BYTES  (3 * G_STAGE_BYTES)    // 165888
// attn smem: 3 stages x (K[128][72] + V[128][72]) bf16
#define A_KROWS   128
#define A_HALF    (A_KROWS * G_PITCHB)       // 18432
#define A_STAGE_BYTES (2 * A_HALF)           // 36864
#define A_SMEM_BYTES  (3 * A_STAGE_BYTES)    // 110592

// ---------------------------------------------------------------------------
// helpers
// ---------------------------------------------------------------------------
__device__ __forceinline__ uint32_t sptr(const void* p) {
    return (uint32_t)__cvta_generic_to_shared(p);
}
__device__ __forceinline__ uint32_t pack_bf16(float lo, float hi) {
    uint32_t d;
    asm("cvt.rn.bf16x2.f32 %0, %1, %2;" : "=r"(d) : "f"(hi), "f"(lo));
    return d;
}
__device__ __forceinline__ void ldsm4(uint32_t& r0, uint32_t& r1, uint32_t& r2, uint32_t& r3,
                                      uint32_t addr) {
    asm volatile("ldmatrix.sync.aligned.m8n8.x4.shared.b16 {%0,%1,%2,%3}, [%4];"
                 : "=r"(r0), "=r"(r1), "=r"(r2), "=r"(r3) : "r"(addr));
}
__device__ __forceinline__ void ldsm4t(uint32_t& r0, uint32_t& r1, uint32_t& r2, uint32_t& r3,
                                       uint32_t addr) {
    asm volatile("ldmatrix.sync.aligned.m8n8.x4.trans.shared.b16 {%0,%1,%2,%3}, [%4];"
                 : "=r"(r0), "=r"(r1), "=r"(r2), "=r"(r3) : "r"(addr));
}
__device__ __forceinline__ void mma16(float* c, const uint32_t* a, uint32_t b0, uint32_t b1) {
    asm volatile("mma.sync.aligned.m16n8k16.row.col.f32.bf16.bf16.f32 "
                 "{%0,%1,%2,%3}, {%4,%5,%6,%7}, {%8,%9}, {%0,%1,%2,%3};"
                 : "+f"(c[0]), "+f"(c[1]), "+f"(c[2]), "+f"(c[3])
                 : "r"(a[0]), "r"(a[1]), "r"(a[2]), "r"(a[3]), "r"(b0), "r"(b1));
}
__device__ __forceinline__ void cpa16(uint32_t dst, const void* src) {
    asm volatile("cp.async.cg.shared.global [%0], [%1], 16;" :: "r"(dst), "l"(src));
}
__device__ __forceinline__ void cp_commit() { asm volatile("cp.async.commit_group;"); }
template<int N> __device__ __forceinline__ void cp_wait() {
    asm volatile("cp.async.wait_group %0;" :: "n"(N));
}

// ---------------------------------------------------------------------------
__global__ void emb_kernel() {
    int idx = blockIdx.x * blockDim.x + threadIdx.x;
    if (idx >= SEQ * HD) return;
    int s = idx / HD, d = idx % HD;
    int i = d & 31;
    double invf = exp(-((double)(2 * i) / 64.0) * log(10000.0));
    double ang = (double)s * invf;
    g_emb[idx] = (float)((d < 32) ? sin(ang) : cos(ang));
}

// all 4 weight matrices fp32 -> bf16 in one launch: grid (1024, 4)
__global__ __launch_bounds__(256) void wcvt_kernel(const float* __restrict__ qw,
                                                   const float* __restrict__ kw,
                                                   const float* __restrict__ vw,
                                                   const float* __restrict__ ow) {
    const int which = blockIdx.y;
    const float* src = (which == 0) ? qw : (which == 1) ? kw : (which == 2) ? vw : ow;
    __nv_bfloat16* dst = (which == 0) ? g_wq : (which == 1) ? g_wk : (which == 2) ? g_wv : g_wo;
    int i = (blockIdx.x * 256 + threadIdx.x) * 4;
    float4 v = *(const float4*)(src + i);
    uint2 o;
    o.x = pack_bf16(v.x, v.y);
    o.y = pack_bf16(v.z, v.w);
    *(uint2*)(dst + i) = o;
}

// ---------------------------------------------------------------------------
__global__ __launch_bounds__(256) void ln_kernel(const float* __restrict__ x,
                                                 const float* __restrict__ gam,
                                                 const float* __restrict__ bet) {
    int row = blockIdx.x;
    const float4* xr = (const float4*)(x + (size_t)row * D_MODEL);
    float4 v = xr[threadIdx.x];
    float sum = v.x + v.y + v.z + v.w;
    float sq  = v.x*v.x + v.y*v.y + v.z*v.z + v.w*v.w;
    #pragma unroll
    for (int o = 16; o; o >>= 1) {
        sum += __shfl_xor_sync(0xFFFFFFFFu, sum, o);
        sq  += __shfl_xor_sync(0xFFFFFFFFu, sq, o);
    }
    __shared__ float ssum[8], ssq[8];
    int w = threadIdx.x >> 5, l = threadIdx.x & 31;
    if (!l) { ssum[w] = sum; ssq[w] = sq; }
    __syncthreads();
    if (w == 0) {
        sum = (l < 8) ? ssum[l] : 0.f;
        sq  = (l < 8) ? ssq[l]  : 0.f;
        #pragma unroll
        for (int o = 4; o; o >>= 1) {
            sum += __shfl_xor_sync(0xFFFFFFFFu, sum, o);
            sq  += __shfl_xor_sync(0xFFFFFFFFu, sq, o);
        }
        if (!l) { ssum[0] = sum; ssq[0] = sq; }
    }
    __syncthreads();
    float mu  = ssum[0] * (1.f / D_MODEL);
    float var = ssq[0] * (1.f / D_MODEL) - mu * mu;
    float rs  = rsqrtf(var + 1e-5f);
    int c = threadIdx.x * 4;
    float4 g4 = *(const float4*)(gam + c);
    float4 b4 = *(const float4*)(bet + c);
    uint2 o;
    o.x = pack_bf16((v.x - mu) * rs * g4.x + b4.x, (v.y - mu) * rs * g4.y + b4.y);
    o.y = pack_bf16((v.z - mu) * rs * g4.z + b4.z, (v.w - mu) * rs * g4.w + b4.w);
    *(uint2*)(g_xln + (size_t)row * D_MODEL + c) = o;
}

// ---------------------------------------------------------------------------
// bf16 GEMM core: CTA 128x256, 512 threads, 16 warps of 64x32 (2m x 8n).
// k-stage 64 (16 iters), 3-stage cp.async ring. Per-thread regs same as R8.
// ---------------------------------------------------------------------------
struct GemmAcc { float a[4][4][4]; };

__device__ __forceinline__ void gemm_core(const __nv_bfloat16* __restrict__ A,
                                          const __nv_bfloat16* __restrict__ B,
                                          int m0, int n0, GemmAcc& G, char* sm) {
    const int tid  = threadIdx.x;
    const int lane = tid & 31, warp = tid >> 5;
    const int wm = warp >> 3, wn = warp & 7;

    #pragma unroll
    for (int mt = 0; mt < 4; mt++)
        #pragma unroll
        for (int nt = 0; nt < 4; nt++)
            #pragma unroll
            for (int j = 0; j < 4; j++) G.a[mt][nt][j] = 0.f;

    auto issue = [&](int st, int k0) {
        char* As = sm + st * G_STAGE_BYTES;
        char* Bs = As + G_ASIZE;
        #pragma unroll
        for (int t = 0; t < 2; t++) {
            int idx = tid + t * 512;           // 0..1023: A 128 rows x 8 chunks
            int row = idx >> 3;
            int cb  = (idx & 7) * 16;
            cpa16(sptr(As + row * G_PITCHB + cb),
                  (const char*)(A + (size_t)(m0 + row) * D_MODEL + k0) + cb);
        }
        #pragma unroll
        for (int t = 0; t < 4; t++) {
            int idx = tid + t * 512;           // 0..2047: B 256 rows x 8 chunks
            int row = idx >> 3;
            int cb  = (idx & 7) * 16;
            cpa16(sptr(Bs + row * G_PITCHB + cb),
                  (const char*)(B + (size_t)(n0 + row) * D_MODEL + k0) + cb);
        }
        cp_commit();
    };

    issue(0, 0);
    issue(1, 64);

    const int arow = (lane & 15);
    const int ahi  = (lane >> 4) * 16;
    const int brow = ((lane >> 4) & 1) * 8 + (lane & 7);
    const int bhi  = ((lane >> 3) & 1) * 16;

    for (int kt = 0; kt < 16; kt++) {
        const int st = kt - (kt / 3) * 3;
        if (kt < 15) cp_wait<1>(); else cp_wait<0>();
        __syncthreads();
        if (kt + 2 < 16) issue((kt + 2) - ((kt + 2) / 3) * 3, (kt + 2) * 64);

        char* As = sm + st * G_STAGE_BYTES;
        char* Bs = As + G_ASIZE;
        #pragma unroll
        for (int ks = 0; ks < 4; ks++) {
            const int kkB = ks * 32;
            uint32_t af[4][4];
            #pragma unroll
            for (int mt = 0; mt < 4; mt++)
                ldsm4(af[mt][0], af[mt][1], af[mt][2], af[mt][3],
                      sptr(As + (wm * 64 + mt * 16 + arow) * G_PITCHB + kkB + ahi));
            uint32_t bf[4][2];
            #pragma unroll
            for (int np = 0; np < 2; np++) {
                uint32_t t0, t1, t2, t3;
                ldsm4(t0, t1, t2, t3,
                      sptr(Bs + (wn * 32 + np * 16 + brow) * G_PITCHB + kkB + bhi));
                bf[np * 2][0] = t0;     bf[np * 2][1] = t1;
                bf[np * 2 + 1][0] = t2; bf[np * 2 + 1][1] = t3;
            }
            #pragma unroll
            for (int mt = 0; mt < 4; mt++)
                #pragma unroll
                for (int nt = 0; nt < 4; nt++)
                    mma16(G.a[mt][nt], af[mt], bf[nt][0], bf[nt][1]);
        }
    }
}

// ---------------------------------------------------------------------------
// QKV proj: grid (12, 64). bx>>2 selects weight, n0 = (bx&3)*256.
// Fused rotary + q scale (0.125*log2e) + head-split.
// ---------------------------------------------------------------------------
__global__ __launch_bounds__(512, 1) void gemm_qkv() {
    extern __shared__ char dynsm_g[];
    const int m0 = blockIdx.y * 128;
    const int which = blockIdx.x >> 2;
    const int n0 = (blockIdx.x & 3) * 256;
    const __nv_bfloat16* W = (which == 0) ? g_wq : (which == 1) ? g_wk : g_wv;

    GemmAcc G;
    gemm_core(g_xln, W, m0, n0, G, dynsm_g);

    const int lane = threadIdx.x & 31, warp = threadIdx.x >> 5;
    const int wm = warp >> 3, wn = warp & 7;
    __nv_bfloat16* dst = (which == 0) ? g_q : (which == 1) ? g_k : g_v;
    const float qscale = 0.125f * 1.4426950408889634f;

    #pragma unroll
    for (int mt = 0; mt < 4; mt++) {
        #pragma unroll
        for (int rh = 0; rh < 2; rh++) {
            int m = m0 + wm * 64 + mt * 16 + rh * 8 + (lane >> 2);
            int b = m >> 11, s = m & 2047;
            #pragma unroll
            for (int nt = 0; nt < 4; nt++) {
                int n  = n0 + wn * 32 + nt * 8 + (lane & 3) * 2;
                int h  = n >> 6, dc = n & 63;
                float ex = 1.f, ey = 1.f;
                if (which < 2) {
                    float2 e = *(const float2*)&g_emb[s * HD + dc];
                    ex = e.x; ey = e.y;
                    if (which == 0) { ex *= qscale; ey *= qscale; }
                }
                uint32_t o = pack_bf16(G.a[mt][nt][rh * 2 + 0] * ex,
                                       G.a[mt][nt][rh * 2 + 1] * ey);
                *(uint32_t*)&dst[((size_t)(b * NHEAD + h) * SEQ + s) * HD + dc] = o;
            }
        }
    }
}

// ---------------------------------------------------------------------------
// out proj + bias + residual: grid (4, 64)
// ---------------------------------------------------------------------------
__global__ __launch_bounds__(512, 1) void gemm_out(const float* __restrict__ ob,
                                                   const float* __restrict__ x,
                                                   float* __restrict__ out) {
    extern __shared__ char dynsm_o[];
    const int m0 = blockIdx.y * 128;
    const int n0 = blockIdx.x * 256;

    GemmAcc G;
    gemm_core(g_ctx, g_wo, m0, n0, G, dynsm_o);

    const int lane = threadIdx.x & 31, warp = threadIdx.x >> 5;
    const int wm = warp >> 3, wn = warp & 7;

    #pragma unroll
    for (int mt = 0; mt < 4; mt++) {
        #pragma unroll
        for (int rh = 0; rh < 2; rh++) {
            int m = m0 + wm * 64 + mt * 16 + rh * 8 + (lane >> 2);
            #pragma unroll
            for (int nt = 0; nt < 4; nt++) {
                int n = n0 + wn * 32 + nt * 8 + (lane & 3) * 2;
                float2 bb = *(const float2*)&ob[n];
                float2 xx = *(const float2*)&x[(size_t)m * D_MODEL + n];
                float2 o;
                o.x = G.a[mt][nt][rh * 2 + 0] + bb.x + xx.x;
                o.y = G.a[mt][nt][rh * 2 + 1] + bb.y + xx.y;
                *(float2*)&out[(size_t)m * D_MODEL + n] = o;
            }
        }
    }
}

// ---------------------------------------------------------------------------
// Flash attention (unchanged from R10). grid (8, 64).
// ---------------------------------------------------------------------------
__global__ __launch_bounds__(256, 2) void attn_kernel(const unsigned char* __restrict__ kpm) {
    extern __shared__ char dynsm_a[];

    const int tid = threadIdx.x, lane = tid & 31, warp = tid >> 5;
    const int bh = blockIdx.y;
    const int batch = bh >> 4, h = bh & 15;

    const __nv_bfloat16* __restrict__ Qg = g_q + (size_t)bh * SEQ * HD;
    const __nv_bfloat16* __restrict__ Kg = g_k + (size_t)bh * SEQ * HD;
    const __nv_bfloat16* __restrict__ Vg = g_v + (size_t)bh * SEQ * HD;
    const unsigned char* __restrict__ maskp = kpm + (size_t)batch * SEQ;

    auto stageK = [&](int st) { return dynsm_a + st * A_STAGE_BYTES; };
    auto stageV = [&](int st) { return dynsm_a + st * A_STAGE_BYTES + A_HALF; };

    auto issue = [&](int st, int kbase) {
        char* Ks = stageK(st);
        char* Vs = stageV(st);
        #pragma unroll
        for (int t = 0; t < 4; t++) {
            int idx = tid + t * 256;
            int row = idx >> 3;
            int cb  = (idx & 7) * 16;
            cpa16(sptr(Ks + row * G_PITCHB + cb),
                  (const char*)(Kg + (size_t)(kbase + row) * HD) + cb);
            cpa16(sptr(Vs + row * G_PITCHB + cb),
                  (const char*)(Vg + (size_t)(kbase + row) * HD) + cb);
        }
        cp_commit();
    };

    const int brow = ((lane >> 4) & 1) * 8 + (lane & 7);
    const int bhi  = ((lane >> 3) & 1) * 16;
    const int vrow = ((lane >> 3) & 1) * 8 + (lane & 7);
    const int vhi  = (lane >> 4) * 16;

    #pragma unroll 1
    for (int ph = 0; ph < 2; ph++) {
        const int qb = ph ? (15 - blockIdx.x) : blockIdx.x;
        const int q0 = qb * 128;
        const int nkb = qb + 1;

        __syncthreads();
        issue(0, 0);
        if (nkb > 1) issue(1, 128);

        uint32_t qf[4][4];
        {
            const int r0 = q0 + warp * 16 + (lane >> 2);
            #pragma unroll
            for (int t = 0; t < 4; t++) {
                int c = t * 16 + (lane & 3) * 2;
                qf[t][0] = *(const uint32_t*)&Qg[(size_t)r0 * HD + c];
                qf[t][1] = *(const uint32_t*)&Qg[(size_t)(r0 + 8) * HD + c];
                qf[t][2] = *(const uint32_t*)&Qg[(size_t)r0 * HD + c + 8];
                qf[t][3] = *(const uint32_t*)&Qg[(size_t)(r0 + 8) * HD + c + 8];
            }
        }

        float o[8][4];
        #pragma unroll
        for (int nt = 0; nt < 8; nt++)
            #pragma unroll
            for (int j = 0; j < 4; j++) o[nt][j] = 0.f;
        float mi0 = -INFINITY, mi1 = -INFINITY, li0 = 0.f, li1 = 0.f;

        #pragma unroll 1
        for (int kb = 0; kb < nkb; kb++) {
            const int st = kb - (kb / 3) * 3;
            if (kb + 1 < nkb) cp_wait<1>(); else cp_wait<0>();
            __syncthreads();
            if (kb + 2 < nkb) issue((kb + 2) - ((kb + 2) / 3) * 3, (kb + 2) * 128);

            const char* Ks = stageK(st);
            const char* Vs = stageV(st);

            #pragma unroll 1
            for (int sub = 0; sub < 2; sub++) {
                const int kbase = kb * 128 + sub * 64;
                const int srow  = sub * 64;
                const bool active = (kbase <= q0 + warp * 16 + 15);
                if (!active) continue;

                float s[8][4];
                #pragma unroll
                for (int nt = 0; nt < 8; nt++)
                    #pragma unroll
                    for (int j = 0; j < 4; j++) s[nt][j] = 0.f;
                #pragma unroll
                for (int ks = 0; ks < 4; ks++) {
                    #pragma unroll
                    for (int np = 0; np < 4; np++) {
                        uint32_t t0, t1, t2, t3;
                        ldsm4(t0, t1, t2, t3,
                              sptr(Ks + (srow + np * 16 + brow) * G_PITCHB + ks * 32 + bhi));
                        mma16(s[np * 2], qf[ks], t0, t1);
                        mma16(s[np * 2 + 1], qf[ks], t2, t3);
                    }
                }

                const int row0 = q0 + warp * 16 + (lane >> 2);
                const bool needc = (kbase + 63) > (q0 + warp * 16);
                #pragma unroll
                for (int nt = 0; nt < 8; nt++) {
                    int c = nt * 8 + (lane & 3) * 2;
                    unsigned char mb0 = maskp[kbase + c], mb1 = maskp[kbase + c + 1];
                    if (mb0) { s[nt][0] = -INFINITY; s[nt][2] = -INFINITY; }
                    if (mb1) { s[nt][1] = -INFINITY; s[nt][3] = -INFINITY; }
                    if (needc) {
                        int cg = kbase + c;
                        if (cg     > row0)     s[nt][0] = -INFINITY;
                        if (cg + 1 > row0)     s[nt][1] = -INFINITY;
                        if (cg     > row0 + 8) s[nt][2] = -INFINITY;
                        if (cg + 1 > row0 + 8) s[nt][3] = -INFINITY;
                    }
                }

                float mx0 = -INFINITY, mx1 = -INFINITY;
                #pragma unroll
                for (int nt = 0; nt < 8; nt++) {
                    mx0 = fmaxf(mx0, fmaxf(s[nt][0], s[nt][1]));
                    mx1 = fmaxf(mx1, fmaxf(s[nt][2], s[nt][3]));
                }
                mx0 = fmaxf(mx0, __shfl_xor_sync(0xFFFFFFFFu, mx0, 1));
                mx0 = fmaxf(mx0, __shfl_xor_sync(0xFFFFFFFFu, mx0, 2));
                mx1 = fmaxf(mx1, __shfl_xor_sync(0xFFFFFFFFu, mx1, 1));
                mx1 = fmaxf(mx1, __shfl_xor_sync(0xFFFFFFFFu, mx1, 2));
                float mt0 = fmaxf(mi0, mx0), mt1 = fmaxf(mi1, mx1);
                float ms0 = (mt0 == -INFINITY) ? 0.f : mt0;
                float ms1 = (mt1 == -INFINITY) ? 0.f : mt1;
                float al0 = exp2f(mi0 - ms0), al1 = exp2f(mi1 - ms1);
                mi0 = mt0; mi1 = mt1;
                float rs0 = 0.f, rs1 = 0.f;
                #pragma unroll
                for (int nt = 0; nt < 8; nt++) {
                    s[nt][0] = exp2f(s[nt][0] - ms0); rs0 += s[nt][0];
                    s[nt][1] = exp2f(s[nt][1] - ms0); rs0 += s[nt][1];
                    s[nt][2] = exp2f(s[nt][2] - ms1); rs1 += s[nt][2];
                    s[nt][3] = exp2f(s[nt][3] - ms1); rs1 += s[nt][3];
                }
                rs0 += __shfl_xor_sync(0xFFFFFFFFu, rs0, 1);
                rs0 += __shfl_xor_sync(0xFFFFFFFFu, rs0, 2);
                rs1 += __shfl_xor_sync(0xFFFFFFFFu, rs1, 1);
                rs1 += __shfl_xor_sync(0xFFFFFFFFu, rs1, 2);
                li0 = li0 * al0 + rs0;
                li1 = li1 * al1 + rs1;
                #pragma unroll
                for (int nt = 0; nt < 8; nt++) {
                    o[nt][0] *= al0; o[nt][1] *= al0;
                    o[nt][2] *= al1; o[nt][3] *= al1;
                }

                #pragma unroll
                for (int t = 0; t < 4; t++) {
                    uint32_t pa[4];
                    pa[0] = pack_bf16(s[2 * t][0],     s[2 * t][1]);
                    pa[1] = pack_bf16(s[2 * t][2],     s[2 * t][3]);
                    pa[2] = pack_bf16(s[2 * t + 1][0], s[2 * t + 1][1]);
                    pa[3] = pack_bf16(s[2 * t + 1][2], s[2 * t + 1][3]);
                    #pragma unroll
                    for (int np = 0; np < 4; np++) {
                        uint32_t t0, t1, t2, t3;
                        ldsm4t(t0, t1, t2, t3,
                               sptr(Vs + (srow + t * 16 + vrow) * G_PITCHB + np * 32 + vhi));
                        mma16(o[np * 2], pa, t0, t1);
                        mma16(o[np * 2 + 1], pa, t2, t3);
                    }
                }
            }
        }

        const float inv0 = 1.f / li0, inv1 = 1.f / li1;
        const int r0 = q0 + warp * 16 + (lane >> 2);
        #pragma unroll
        for (int nt = 0; nt < 8; nt++) {
            int dc = nt * 8 + (lane & 3) * 2;
            uint32_t w0 = pack_bf16(o[nt][0] * inv0, o[nt][1] * inv0);
            uint32_t w1 = pack_bf16(o[nt][2] * inv1, o[nt][3] * inv1);
            *(uint32_t*)&g_ctx[(size_t)(batch * SEQ + r0) * D_MODEL + h * HD + dc] = w0;
            *(uint32_t*)&g_ctx[(size_t)(batch * SEQ + r0 + 8) * D_MODEL + h * HD + dc] = w1;
        }
    }
}

// ---------------------------------------------------------------------------
extern "C" void kernel_launch(void* const* d_in, const int* in_sizes, int n_in,
                              void* d_out, int out_size) {
    const float* x  = (const float*)d_in[0];
    const unsigned char* kpm = (const unsigned char*)d_in[1];
    const float* qw = (const float*)d_in[2];
    const float* kw = (const float*)d_in[3];
    const float* vw = (const float*)d_in[4];
    const float* ow = (const float*)d_in[5];
    const float* ob = (const float*)d_in[6];
    const float* lg = (const float*)d_in[7];
    const float* lb = (const float*)d_in[8];
    float* out = (float*)d_out;

    static bool attr_done = false;
    if (!attr_done) {
        cudaFuncSetAttribute(gemm_qkv, cudaFuncAttributeMaxDynamicSharedMemorySize, G_SMEM_BYTES);
        cudaFuncSetAttribute(gemm_out, cudaFuncAttributeMaxDynamicSharedMemorySize, G_SMEM_BYTES);
        cudaFuncSetAttribute(attn_kernel, cudaFuncAttributeMaxDynamicSharedMemorySize, A_SMEM_BYTES);
        attr_done = true;
    }

    emb_kernel<<<(SEQ * HD + 255) / 256, 256>>>();
    wcvt_kernel<<<dim3(D_MODEL * D_MODEL / (256 * 4), 4), 256>>>(qw, kw, vw, ow);
    ln_kernel<<<MTOT, 256>>>(x, lg, lb);
    gemm_qkv<<<dim3(12, 64), 512, G_SMEM_BYTES>>>();
    attn_kernel<<<dim3(8, 64), 256, A_SMEM_BYTES>>>(kpm);
    gemm_out<<<dim3(4, 64), 512, G_SMEM_BYTES>>>(ob, x, out);
}

// round 12
// speedup vs baseline: 1.0472x; 1.0472x over previous
#include <cuda_runtime.h>
#include <cuda_bf16.h>
#include <cstdint>
#include <math.h>

#define D_MODEL 1024
#define NHEAD   16
#define HD      64
#define SEQ     2048
#define BATCH   4
#define MTOT    (BATCH*SEQ)      // 8192
#define BHN     (BATCH*NHEAD)    // 64

static __device__ __nv_bfloat16 g_xln[MTOT * D_MODEL];
static __device__ __nv_bfloat16 g_q[BHN * SEQ * HD];
static __device__ __nv_bfloat16 g_k[BHN * SEQ * HD];
static __device__ __nv_bfloat16 g_v[BHN * SEQ * HD];
static __device__ __nv_bfloat16 g_ctx[MTOT * D_MODEL];
static __device__ __nv_bfloat16 g_wq[D_MODEL * D_MODEL];
static __device__ __nv_bfloat16 g_wk[D_MODEL * D_MODEL];
static __device__ __nv_bfloat16 g_wv[D_MODEL * D_MODEL];
static __device__ __nv_bfloat16 g_wo[D_MODEL * D_MODEL];
static __device__ float g_emb[SEQ * HD];

// qkv GEMM smem: 3 stages x (A[128] + B[128]) rows of 72 bf16 (144B pitch)
#define G_PITCHB  144
#define G_ASIZE   (128 * G_PITCHB)          // 18432
#define G_STAGE_BYTES (2 * G_ASIZE)          // 36864
#define G_SMEM_BYTES  (3 * G_STAGE_BYTES)    // 110592
// out GEMM smem: 3 stages x (A[64] + B[128]) rows
#define GO_ASIZE  (64 * G_PITCHB)            // 9216
#define GO_STAGE_BYTES (GO_ASIZE + G_ASIZE)  // 27648
#define GO_SMEM_BYTES  (3 * GO_STAGE_BYTES)  // 82944
// attn smem: 3 stages x (K[128][72] + V[128][72]) bf16
#define A_KROWS   128
#define A_HALF    (A_KROWS * G_PITCHB)       // 18432
#define A_STAGE_BYTES (2 * A_HALF)           // 36864
#define A_SMEM_BYTES  (3 * A_STAGE_BYTES)    // 110592

// ---------------------------------------------------------------------------
// helpers
// ---------------------------------------------------------------------------
__device__ __forceinline__ uint32_t sptr(const void* p) {
    return (uint32_t)__cvta_generic_to_shared(p);
}
__device__ __forceinline__ uint32_t pack_bf16(float lo, float hi) {
    uint32_t d;
    asm("cvt.rn.bf16x2.f32 %0, %1, %2;" : "=r"(d) : "f"(hi), "f"(lo));
    return d;
}
__device__ __forceinline__ void ldsm4(uint32_t& r0, uint32_t& r1, uint32_t& r2, uint32_t& r3,
                                      uint32_t addr) {
    asm volatile("ldmatrix.sync.aligned.m8n8.x4.shared.b16 {%0,%1,%2,%3}, [%4];"
                 : "=r"(r0), "=r"(r1), "=r"(r2), "=r"(r3) : "r"(addr));
}
__device__ __forceinline__ void ldsm4t(uint32_t& r0, uint32_t& r1, uint32_t& r2, uint32_t& r3,
                                       uint32_t addr) {
    asm volatile("ldmatrix.sync.aligned.m8n8.x4.trans.shared.b16 {%0,%1,%2,%3}, [%4];"
                 : "=r"(r0), "=r"(r1), "=r"(r2), "=r"(r3) : "r"(addr));
}
__device__ __forceinline__ void mma16(float* c, const uint32_t* a, uint32_t b0, uint32_t b1) {
    asm volatile("mma.sync.aligned.m16n8k16.row.col.f32.bf16.bf16.f32 "
                 "{%0,%1,%2,%3}, {%4,%5,%6,%7}, {%8,%9}, {%0,%1,%2,%3};"
                 : "+f"(c[0]), "+f"(c[1]), "+f"(c[2]), "+f"(c[3])
                 : "r"(a[0]), "r"(a[1]), "r"(a[2]), "r"(a[3]), "r"(b0), "r"(b1));
}
__device__ __forceinline__ void cpa16(uint32_t dst, const void* src) {
    asm volatile("cp.async.cg.shared.global [%0], [%1], 16;" :: "r"(dst), "l"(src));
}
__device__ __forceinline__ void cp_commit() { asm volatile("cp.async.commit_group;"); }
template<int N> __device__ __forceinline__ void cp_wait() {
    asm volatile("cp.async.wait_group %0;" :: "n"(N));
}

// ---------------------------------------------------------------------------
__global__ void emb_kernel() {
    int idx = blockIdx.x * blockDim.x + threadIdx.x;
    if (idx >= SEQ * HD) return;
    int s = idx / HD, d = idx % HD;
    int i = d & 31;
    double invf = exp(-((double)(2 * i) / 64.0) * log(10000.0));
    double ang = (double)s * invf;
    g_emb[idx] = (float)((d < 32) ? sin(ang) : cos(ang));
}

// all 4 weight matrices fp32 -> bf16 in one launch: grid (1024, 4)
__global__ __launch_bounds__(256) void wcvt_kernel(const float* __restrict__ qw,
                                                   const float* __restrict__ kw,
                                                   const float* __restrict__ vw,
                                                   const float* __restrict__ ow) {
    const int which = blockIdx.y;
    const float* src = (which == 0) ? qw : (which == 1) ? kw : (which == 2) ? vw : ow;
    __nv_bfloat16* dst = (which == 0) ? g_wq : (which == 1) ? g_wk : (which == 2) ? g_wv : g_wo;
    int i = (blockIdx.x * 256 + threadIdx.x) * 4;
    float4 v = *(const float4*)(src + i);
    uint2 o;
    o.x = pack_bf16(v.x, v.y);
    o.y = pack_bf16(v.z, v.w);
    *(uint2*)(dst + i) = o;
}

// ---------------------------------------------------------------------------
__global__ __launch_bounds__(256) void ln_kernel(const float* __restrict__ x,
                                                 const float* __restrict__ gam,
                                                 const float* __restrict__ bet) {
    int row = blockIdx.x;
    const float4* xr = (const float4*)(x + (size_t)row * D_MODEL);
    float4 v = xr[threadIdx.x];
    float sum = v.x + v.y + v.z + v.w;
    float sq  = v.x*v.x + v.y*v.y + v.z*v.z + v.w*v.w;
    #pragma unroll
    for (int o = 16; o; o >>= 1) {
        sum += __shfl_xor_sync(0xFFFFFFFFu, sum, o);
        sq  += __shfl_xor_sync(0xFFFFFFFFu, sq, o);
    }
    __shared__ float ssum[8], ssq[8];
    int w = threadIdx.x >> 5, l = threadIdx.x & 31;
    if (!l) { ssum[w] = sum; ssq[w] = sq; }
    __syncthreads();
    if (w == 0) {
        sum = (l < 8) ? ssum[l] : 0.f;
        sq  = (l < 8) ? ssq[l]  : 0.f;
        #pragma unroll
        for (int o = 4; o; o >>= 1) {
            sum += __shfl_xor_sync(0xFFFFFFFFu, sum, o);
            sq  += __shfl_xor_sync(0xFFFFFFFFu, sq, o);
        }
        if (!l) { ssum[0] = sum; ssq[0] = sq; }
    }
    __syncthreads();
    float mu  = ssum[0] * (1.f / D_MODEL);
    float var = ssq[0] * (1.f / D_MODEL) - mu * mu;
    float rs  = rsqrtf(var + 1e-5f);
    int c = threadIdx.x * 4;
    float4 g4 = *(const float4*)(gam + c);
    float4 b4 = *(const float4*)(bet + c);
    uint2 o;
    o.x = pack_bf16((v.x - mu) * rs * g4.x + b4.x, (v.y - mu) * rs * g4.y + b4.y);
    o.y = pack_bf16((v.z - mu) * rs * g4.z + b4.z, (v.w - mu) * rs * g4.w + b4.w);
    *(uint2*)(g_xln + (size_t)row * D_MODEL + c) = o;
}

// ---------------------------------------------------------------------------
// bf16 GEMM core (R8/R10 config): CTA 128x128, k-stage 64 (16 iters), 3-stage ring.
// ---------------------------------------------------------------------------
struct GemmAcc { float a[4][4][4]; };

__device__ __forceinline__ void gemm_core(const __nv_bfloat16* __restrict__ A,
                                          const __nv_bfloat16* __restrict__ B,
                                          int m0, int n0, GemmAcc& G, char* sm) {
    const int tid  = threadIdx.x;
    const int lane = tid & 31, warp = tid >> 5;
    const int wm = warp >> 2, wn = warp & 3;

    #pragma unroll
    for (int mt = 0; mt < 4; mt++)
        #pragma unroll
        for (int nt = 0; nt < 4; nt++)
            #pragma unroll
            for (int j = 0; j < 4; j++) G.a[mt][nt][j] = 0.f;

    auto issue = [&](int st, int k0) {
        char* As = sm + st * G_STAGE_BYTES;
        char* Bs = As + G_ASIZE;
        #pragma unroll
        for (int t = 0; t < 4; t++) {
            int idx = tid + t * 256;
            int row = idx >> 3;
            int cb  = (idx & 7) * 16;
            cpa16(sptr(As + row * G_PITCHB + cb),
                  (const char*)(A + (size_t)(m0 + row) * D_MODEL + k0) + cb);
            cpa16(sptr(Bs + row * G_PITCHB + cb),
                  (const char*)(B + (size_t)(n0 + row) * D_MODEL + k0) + cb);
        }
        cp_commit();
    };

    issue(0, 0);
    issue(1, 64);

    const int arow = (lane & 15);
    const int ahi  = (lane >> 4) * 16;
    const int brow = ((lane >> 4) & 1) * 8 + (lane & 7);
    const int bhi  = ((lane >> 3) & 1) * 16;

    for (int kt = 0; kt < 16; kt++) {
        const int st = kt - (kt / 3) * 3;
        if (kt < 15) cp_wait<1>(); else cp_wait<0>();
        __syncthreads();
        if (kt + 2 < 16) issue((kt + 2) - ((kt + 2) / 3) * 3, (kt + 2) * 64);

        char* As = sm + st * G_STAGE_BYTES;
        char* Bs = As + G_ASIZE;
        #pragma unroll
        for (int ks = 0; ks < 4; ks++) {
            const int kkB = ks * 32;
            uint32_t af[4][4];
            #pragma unroll
            for (int mt = 0; mt < 4; mt++)
                ldsm4(af[mt][0], af[mt][1], af[mt][2], af[mt][3],
                      sptr(As + (wm * 64 + mt * 16 + arow) * G_PITCHB + kkB + ahi));
            uint32_t bf[4][2];
            #pragma unroll
            for (int np = 0; np < 2; np++) {
                uint32_t t0, t1, t2, t3;
                ldsm4(t0, t1, t2, t3,
                      sptr(Bs + (wn * 32 + np * 16 + brow) * G_PITCHB + kkB + bhi));
                bf[np * 2][0] = t0;     bf[np * 2][1] = t1;
                bf[np * 2 + 1][0] = t2; bf[np * 2 + 1][1] = t3;
            }
            #pragma unroll
            for (int mt = 0; mt < 4; mt++)
                #pragma unroll
                for (int nt = 0; nt < 4; nt++)
                    mma16(G.a[mt][nt], af[mt], bf[nt][0], bf[nt][1]);
        }
    }
}

// ---------------------------------------------------------------------------
// QKV proj: grid (24, 64). Fused rotary + q scale (0.125*log2e) + head-split.
// ---------------------------------------------------------------------------
__global__ __launch_bounds__(256, 2) void gemm_qkv() {
    extern __shared__ char dynsm_g[];
    const int m0 = blockIdx.y * 128;
    const int which = blockIdx.x >> 3;
    const int n0 = (blockIdx.x & 7) * 128;
    const __nv_bfloat16* W = (which == 0) ? g_wq : (which == 1) ? g_wk : g_wv;

    GemmAcc G;
    gemm_core(g_xln, W, m0, n0, G, dynsm_g);

    const int lane = threadIdx.x & 31, warp = threadIdx.x >> 5;
    const int wm = warp >> 2, wn = warp & 3;
    __nv_bfloat16* dst = (which == 0) ? g_q : (which == 1) ? g_k : g_v;
    const float qscale = 0.125f * 1.4426950408889634f;

    #pragma unroll
    for (int mt = 0; mt < 4; mt++) {
        #pragma unroll
        for (int rh = 0; rh < 2; rh++) {
            int m = m0 + wm * 64 + mt * 16 + rh * 8 + (lane >> 2);
            int b = m >> 11, s = m & 2047;
            #pragma unroll
            for (int nt = 0; nt < 4; nt++) {
                int n  = n0 + wn * 32 + nt * 8 + (lane & 3) * 2;
                int h  = n >> 6, dc = n & 63;
                float ex = 1.f, ey = 1.f;
                if (which < 2) {
                    float2 e = *(const float2*)&g_emb[s * HD + dc];
                    ex = e.x; ey = e.y;
                    if (which == 0) { ex *= qscale; ey *= qscale; }
                }
                uint32_t o = pack_bf16(G.a[mt][nt][rh * 2 + 0] * ex,
                                       G.a[mt][nt][rh * 2 + 1] * ey);
                *(uint32_t*)&dst[((size_t)(b * NHEAD + h) * SEQ + s) * HD + dc] = o;
            }
        }
    }
}

// ---------------------------------------------------------------------------
// out proj + bias + residual: 64x128 tiles, grid (8, 128) -> 1024 CTAs
// (3.46 waves vs 1.73 -> less tail waste). 8 warps of 32x32 (2m x 4n).
// ---------------------------------------------------------------------------
__global__ __launch_bounds__(256, 2) void gemm_out(const float* __restrict__ ob,
                                                   const float* __restrict__ x,
                                                   float* __restrict__ out) {
    extern __shared__ char dynsm_o[];
    const int m0 = blockIdx.y * 64;
    const int n0 = blockIdx.x * 128;
    const int tid  = threadIdx.x;
    const int lane = tid & 31, warp = tid >> 5;
    const int wm = warp >> 2, wn = warp & 3;
    const __nv_bfloat16* __restrict__ A = g_ctx;
    const __nv_bfloat16* __restrict__ B = g_wo;

    float acc[2][4][4];
    #pragma unroll
    for (int mt = 0; mt < 2; mt++)
        #pragma unroll
        for (int nt = 0; nt < 4; nt++)
            #pragma unroll
            for (int j = 0; j < 4; j++) acc[mt][nt][j] = 0.f;

    auto issue = [&](int st, int k0) {
        char* As = dynsm_o + st * GO_STAGE_BYTES;
        char* Bs = As + GO_ASIZE;
        #pragma unroll
        for (int t = 0; t < 2; t++) {
            int idx = tid + t * 256;          // 0..511: A 64 rows x 8 chunks
            int row = idx >> 3;
            int cb  = (idx & 7) * 16;
            cpa16(sptr(As + row * G_PITCHB + cb),
                  (const char*)(A + (size_t)(m0 + row) * D_MODEL + k0) + cb);
        }
        #pragma unroll
        for (int t = 0; t < 4; t++) {
            int idx = tid + t * 256;          // 0..1023: B 128 rows x 8 chunks
            int row = idx >> 3;
            int cb  = (idx & 7) * 16;
            cpa16(sptr(Bs + row * G_PITCHB + cb),
                  (const char*)(B + (size_t)(n0 + row) * D_MODEL + k0) + cb);
        }
        cp_commit();
    };

    issue(0, 0);
    issue(1, 64);

    const int arow = (lane & 15);
    const int ahi  = (lane >> 4) * 16;
    const int brow = ((lane >> 4) & 1) * 8 + (lane & 7);
    const int bhi  = ((lane >> 3) & 1) * 16;

    for (int kt = 0; kt < 16; kt++) {
        const int st = kt - (kt / 3) * 3;
        if (kt < 15) cp_wait<1>(); else cp_wait<0>();
        __syncthreads();
        if (kt + 2 < 16) issue((kt + 2) - ((kt + 2) / 3) * 3, (kt + 2) * 64);

        char* As = dynsm_o + st * GO_STAGE_BYTES;
        char* Bs = As + GO_ASIZE;
        #pragma unroll
        for (int ks = 0; ks < 4; ks++) {
            const int kkB = ks * 32;
            uint32_t af[2][4];
            #pragma unroll
            for (int mt = 0; mt < 2; mt++)
                ldsm4(af[mt][0], af[mt][1], af[mt][2], af[mt][3],
                      sptr(As + (wm * 32 + mt * 16 + arow) * G_PITCHB + kkB + ahi));
            uint32_t bf[4][2];
            #pragma unroll
            for (int np = 0; np < 2; np++) {
                uint32_t t0, t1, t2, t3;
                ldsm4(t0, t1, t2, t3,
                      sptr(Bs + (wn * 32 + np * 16 + brow) * G_PITCHB + kkB + bhi));
                bf[np * 2][0] = t0;     bf[np * 2][1] = t1;
                bf[np * 2 + 1][0] = t2; bf[np * 2 + 1][1] = t3;
            }
            #pragma unroll
            for (int mt = 0; mt < 2; mt++)
                #pragma unroll
                for (int nt = 0; nt < 4; nt++)
                    mma16(acc[mt][nt], af[mt], bf[nt][0], bf[nt][1]);
        }
    }

    #pragma unroll
    for (int mt = 0; mt < 2; mt++) {
        #pragma unroll
        for (int rh = 0; rh < 2; rh++) {
            int m = m0 + wm * 32 + mt * 16 + rh * 8 + (lane >> 2);
            #pragma unroll
            for (int nt = 0; nt < 4; nt++) {
                int n = n0 + wn * 32 + nt * 8 + (lane & 3) * 2;
                float2 bb = *(const float2*)&ob[n];
                float2 xx = *(const float2*)&x[(size_t)m * D_MODEL + n];
                float2 o;
                o.x = acc[mt][nt][rh * 2 + 0] + bb.x + xx.x;
                o.y = acc[mt][nt][rh * 2 + 1] + bb.y + xx.y;
                *(float2*)&out[(size_t)m * D_MODEL + n] = o;
            }
        }
    }
}

// ---------------------------------------------------------------------------
// Flash attention (R10 exact). grid (8, 64).
// ---------------------------------------------------------------------------
__global__ __launch_bounds__(256, 2) void attn_kernel(const unsigned char* __restrict__ kpm) {
    extern __shared__ char dynsm_a[];

    const int tid = threadIdx.x, lane = tid & 31, warp = tid >> 5;
    const int bh = blockIdx.y;
    const int batch = bh >> 4, h = bh & 15;

    const __nv_bfloat16* __restrict__ Qg = g_q + (size_t)bh * SEQ * HD;
    const __nv_bfloat16* __restrict__ Kg = g_k + (size_t)bh * SEQ * HD;
    const __nv_bfloat16* __restrict__ Vg = g_v + (size_t)bh * SEQ * HD;
    const unsigned char* __restrict__ maskp = kpm + (size_t)batch * SEQ;

    auto stageK = [&](int st) { return dynsm_a + st * A_STAGE_BYTES; };
    auto stageV = [&](int st) { return dynsm_a + st * A_STAGE_BYTES + A_HALF; };

    auto issue = [&](int st, int kbase) {
        char* Ks = stageK(st);
        char* Vs = stageV(st);
        #pragma unroll
        for (int t = 0; t < 4; t++) {
            int idx = tid + t * 256;
            int row = idx >> 3;
            int cb  = (idx & 7) * 16;
            cpa16(sptr(Ks + row * G_PITCHB + cb),
                  (const char*)(Kg + (size_t)(kbase + row) * HD) + cb);
            cpa16(sptr(Vs + row * G_PITCHB + cb),
                  (const char*)(Vg + (size_t)(kbase + row) * HD) + cb);
        }
        cp_commit();
    };

    const int brow = ((lane >> 4) & 1) * 8 + (lane & 7);
    const int bhi  = ((lane >> 3) & 1) * 16;
    const int vrow = ((lane >> 3) & 1) * 8 + (lane & 7);
    const int vhi  = (lane >> 4) * 16;

    #pragma unroll 1
    for (int ph = 0; ph < 2; ph++) {
        const int qb = ph ? (15 - blockIdx.x) : blockIdx.x;
        const int q0 = qb * 128;
        const int nkb = qb + 1;

        __syncthreads();
        issue(0, 0);
        if (nkb > 1) issue(1, 128);

        uint32_t qf[4][4];
        {
            const int r0 = q0 + warp * 16 + (lane >> 2);
            #pragma unroll
            for (int t = 0; t < 4; t++) {
                int c = t * 16 + (lane & 3) * 2;
                qf[t][0] = *(const uint32_t*)&Qg[(size_t)r0 * HD + c];
                qf[t][1] = *(const uint32_t*)&Qg[(size_t)(r0 + 8) * HD + c];
                qf[t][2] = *(const uint32_t*)&Qg[(size_t)r0 * HD + c + 8];
                qf[t][3] = *(const uint32_t*)&Qg[(size_t)(r0 + 8) * HD + c + 8];
            }
        }

        float o[8][4];
        #pragma unroll
        for (int nt = 0; nt < 8; nt++)
            #pragma unroll
            for (int j = 0; j < 4; j++) o[nt][j] = 0.f;
        float mi0 = -INFINITY, mi1 = -INFINITY, li0 = 0.f, li1 = 0.f;

        #pragma unroll 1
        for (int kb = 0; kb < nkb; kb++) {
            const int st = kb - (kb / 3) * 3;
            if (kb + 1 < nkb) cp_wait<1>(); else cp_wait<0>();
            __syncthreads();
            if (kb + 2 < nkb) issue((kb + 2) - ((kb + 2) / 3) * 3, (kb + 2) * 128);

            const char* Ks = stageK(st);
            const char* Vs = stageV(st);

            #pragma unroll 1
            for (int sub = 0; sub < 2; sub++) {
                const int kbase = kb * 128 + sub * 64;
                const int srow  = sub * 64;
                const bool active = (kbase <= q0 + warp * 16 + 15);
                if (!active) continue;

                float s[8][4];
                #pragma unroll
                for (int nt = 0; nt < 8; nt++)
                    #pragma unroll
                    for (int j = 0; j < 4; j++) s[nt][j] = 0.f;
                #pragma unroll
                for (int ks = 0; ks < 4; ks++) {
                    #pragma unroll
                    for (int np = 0; np < 4; np++) {
                        uint32_t t0, t1, t2, t3;
                        ldsm4(t0, t1, t2, t3,
                              sptr(Ks + (srow + np * 16 + brow) * G_PITCHB + ks * 32 + bhi));
                        mma16(s[np * 2], qf[ks], t0, t1);
                        mma16(s[np * 2 + 1], qf[ks], t2, t3);
                    }
                }

                const int row0 = q0 + warp * 16 + (lane >> 2);
                const bool needc = (kbase + 63) > (q0 + warp * 16);
                #pragma unroll
                for (int nt = 0; nt < 8; nt++) {
                    int c = nt * 8 + (lane & 3) * 2;
                    unsigned char mb0 = maskp[kbase + c], mb1 = maskp[kbase + c + 1];
                    if (mb0) { s[nt][0] = -INFINITY; s[nt][2] = -INFINITY; }
                    if (mb1) { s[nt][1] = -INFINITY; s[nt][3] = -INFINITY; }
                    if (needc) {
                        int cg = kbase + c;
                        if (cg     > row0)     s[nt][0] = -INFINITY;
                        if (cg + 1 > row0)     s[nt][1] = -INFINITY;
                        if (cg     > row0 + 8) s[nt][2] = -INFINITY;
                        if (cg + 1 > row0 + 8) s[nt][3] = -INFINITY;
                    }
                }

                float mx0 = -INFINITY, mx1 = -INFINITY;
                #pragma unroll
                for (int nt = 0; nt < 8; nt++) {
                    mx0 = fmaxf(mx0, fmaxf(s[nt][0], s[nt][1]));
                    mx1 = fmaxf(mx1, fmaxf(s[nt][2], s[nt][3]));
                }
                mx0 = fmaxf(mx0, __shfl_xor_sync(0xFFFFFFFFu, mx0, 1));
                mx0 = fmaxf(mx0, __shfl_xor_sync(0xFFFFFFFFu, mx0, 2));
                mx1 = fmaxf(mx1, __shfl_xor_sync(0xFFFFFFFFu, mx1, 1));
                mx1 = fmaxf(mx1, __shfl_xor_sync(0xFFFFFFFFu, mx1, 2));
                float mt0 = fmaxf(mi0, mx0), mt1 = fmaxf(mi1, mx1);
                float ms0 = (mt0 == -INFINITY) ? 0.f : mt0;
                float ms1 = (mt1 == -INFINITY) ? 0.f : mt1;
                float al0 = exp2f(mi0 - ms0), al1 = exp2f(mi1 - ms1);
                mi0 = mt0; mi1 = mt1;
                float rs0 = 0.f, rs1 = 0.f;
                #pragma unroll
                for (int nt = 0; nt < 8; nt++) {
                    s[nt][0] = exp2f(s[nt][0] - ms0); rs0 += s[nt][0];
                    s[nt][1] = exp2f(s[nt][1] - ms0); rs0 += s[nt][1];
                    s[nt][2] = exp2f(s[nt][2] - ms1); rs1 += s[nt][2];
                    s[nt][3] = exp2f(s[nt][3] - ms1); rs1 += s[nt][3];
                }
                rs0 += __shfl_xor_sync(0xFFFFFFFFu, rs0, 1);
                rs0 += __shfl_xor_sync(0xFFFFFFFFu, rs0, 2);
                rs1 += __shfl_xor_sync(0xFFFFFFFFu, rs1, 1);
                rs1 += __shfl_xor_sync(0xFFFFFFFFu, rs1, 2);
                li0 = li0 * al0 + rs0;
                li1 = li1 * al1 + rs1;
                #pragma unroll
                for (int nt = 0; nt < 8; nt++) {
                    o[nt][0] *= al0; o[nt][1] *= al0;
                    o[nt][2] *= al1; o[nt][3] *= al1;
                }

                #pragma unroll
                for (int t = 0; t < 4; t++) {
                    uint32_t pa[4];
                    pa[0] = pack_bf16(s[2 * t][0],     s[2 * t][1]);
                    pa[1] = pack_bf16(s[2 * t][2],     s[2 * t][3]);
                    pa[2] = pack_bf16(s[2 * t + 1][0], s[2 * t + 1][1]);
                    pa[3] = pack_bf16(s[2 * t + 1][2], s[2 * t + 1][3]);
                    #pragma unroll
                    for (int np = 0; np < 4; np++) {
                        uint32_t t0, t1, t2, t3;
                        ldsm4t(t0, t1, t2, t3,
                               sptr(Vs + (srow + t * 16 + vrow) * G_PITCHB + np * 32 + vhi));
                        mma16(o[np * 2], pa, t0, t1);
                        mma16(o[np * 2 + 1], pa, t2, t3);
                    }
                }
            }
        }

        const float inv0 = 1.f / li0, inv1 = 1.f / li1;
        const int r0 = q0 + warp * 16 + (lane >> 2);
        #pragma unroll
        for (int nt = 0; nt < 8; nt++) {
            int dc = nt * 8 + (lane & 3) * 2;
            uint32_t w0 = pack_bf16(o[nt][0] * inv0, o[nt][1] * inv0);
            uint32_t w1 = pack_bf16(o[nt][2] * inv1, o[nt][3] * inv1);
            *(uint32_t*)&g_ctx[(size_t)(batch * SEQ + r0) * D_MODEL + h * HD + dc] = w0;
            *(uint32_t*)&g_ctx[(size_t)(batch * SEQ + r0 + 8) * D_MODEL + h * HD + dc] = w1;
        }
    }
}

// ---------------------------------------------------------------------------
extern "C" void kernel_launch(void* const* d_in, const int* in_sizes, int n_in,
                              void* d_out, int out_size) {
    const float* x  = (const float*)d_in[0];
    const unsigned char* kpm = (const unsigned char*)d_in[1];
    const float* qw = (const float*)d_in[2];
    const float* kw = (const float*)d_in[3];
    const float* vw = (const float*)d_in[4];
    const float* ow = (const float*)d_in[5];
    const float* ob = (const float*)d_in[6];
    const float* lg = (const float*)d_in[7];
    const float* lb = (const float*)d_in[8];
    float* out = (float*)d_out;

    static bool attr_done = false;
    if (!attr_done) {
        cudaFuncSetAttribute(gemm_qkv, cudaFuncAttributeMaxDynamicSharedMemorySize, G_SMEM_BYTES);
        cudaFuncSetAttribute(gemm_out, cudaFuncAttributeMaxDynamicSharedMemorySize, GO_SMEM_BYTES);
        cudaFuncSetAttribute(attn_kernel, cudaFuncAttributeMaxDynamicSharedMemorySize, A_SMEM_BYTES);
        attr_done = true;
    }

    emb_kernel<<<(SEQ * HD + 255) / 256, 256>>>();
    wcvt_kernel<<<dim3(D_MODEL * D_MODEL / (256 * 4), 4), 256>>>(qw, kw, vw, ow);
    ln_kernel<<<MTOT, 256>>>(x, lg, lb);
    gemm_qkv<<<dim3(24, 64), 256, G_SMEM_BYTES>>>();
    attn_kernel<<<dim3(8, 64), 256, A_SMEM_BYTES>>>(kpm);
    gemm_out<<<dim3(8, 128), 256, GO_SMEM_BYTES>>>(ob, x, out);
}

// round 13
// speedup vs baseline: 1.0762x; 1.0277x over previous
#include <cuda_runtime.h>
#include <cuda_bf16.h>
#include <cstdint>
#include <math.h>

#define D_MODEL 1024
#define NHEAD   16
#define HD      64
#define SEQ     2048
#define BATCH   4
#define MTOT    (BATCH*SEQ)      // 8192
#define BHN     (BATCH*NHEAD)    // 64

static __device__ __nv_bfloat16 g_xln[MTOT * D_MODEL];
static __device__ __nv_bfloat16 g_q[BHN * SEQ * HD];
static __device__ __nv_bfloat16 g_k[BHN * SEQ * HD];
static __device__ __nv_bfloat16 g_v[BHN * SEQ * HD];
static __device__ __nv_bfloat16 g_ctx[MTOT * D_MODEL];
static __device__ __nv_bfloat16 g_wq[D_MODEL * D_MODEL];
static __device__ __nv_bfloat16 g_wk[D_MODEL * D_MODEL];
static __device__ __nv_bfloat16 g_wv[D_MODEL * D_MODEL];
static __device__ __nv_bfloat16 g_wo[D_MODEL * D_MODEL];
static __device__ float g_emb[SEQ * HD];

// GEMM smem: 3 stages x (A[128] + B[128]) rows of 72 bf16 (144B pitch)
#define G_PITCHB  144
#define G_ASIZE   (128 * G_PITCHB)          // 18432
#define G_STAGE_BYTES (2 * G_ASIZE)          // 36864
#define G_SMEM_BYTES  (3 * G_STAGE_BYTES)    // 110592
// attn smem: 3 stages x (K[128][72] + V[128][72]) bf16 + mask[2048]
#define A_KROWS   128
#define A_HALF    (A_KROWS * G_PITCHB)       // 18432
#define A_STAGE_BYTES (2 * A_HALF)           // 36864
#define A_MASK_OFF (3 * A_STAGE_BYTES)       // 110592
#define A_SMEM_BYTES  (A_MASK_OFF + 2048)    // 112640

// ---------------------------------------------------------------------------
// helpers
// ---------------------------------------------------------------------------
__device__ __forceinline__ uint32_t sptr(const void* p) {
    return (uint32_t)__cvta_generic_to_shared(p);
}
__device__ __forceinline__ uint32_t pack_bf16(float lo, float hi) {
    uint32_t d;
    asm("cvt.rn.bf16x2.f32 %0, %1, %2;" : "=r"(d) : "f"(hi), "f"(lo));
    return d;
}
__device__ __forceinline__ void ldsm4(uint32_t& r0, uint32_t& r1, uint32_t& r2, uint32_t& r3,
                                      uint32_t addr) {
    asm volatile("ldmatrix.sync.aligned.m8n8.x4.shared.b16 {%0,%1,%2,%3}, [%4];"
                 : "=r"(r0), "=r"(r1), "=r"(r2), "=r"(r3) : "r"(addr));
}
__device__ __forceinline__ void ldsm4t(uint32_t& r0, uint32_t& r1, uint32_t& r2, uint32_t& r3,
                                       uint32_t addr) {
    asm volatile("ldmatrix.sync.aligned.m8n8.x4.trans.shared.b16 {%0,%1,%2,%3}, [%4];"
                 : "=r"(r0), "=r"(r1), "=r"(r2), "=r"(r3) : "r"(addr));
}
__device__ __forceinline__ void mma16(float* c, const uint32_t* a, uint32_t b0, uint32_t b1) {
    asm volatile("mma.sync.aligned.m16n8k16.row.col.f32.bf16.bf16.f32 "
                 "{%0,%1,%2,%3}, {%4,%5,%6,%7}, {%8,%9}, {%0,%1,%2,%3};"
                 : "+f"(c[0]), "+f"(c[1]), "+f"(c[2]), "+f"(c[3])
                 : "r"(a[0]), "r"(a[1]), "r"(a[2]), "r"(a[3]), "r"(b0), "r"(b1));
}
__device__ __forceinline__ void cpa16(uint32_t dst, const void* src) {
    asm volatile("cp.async.cg.shared.global [%0], [%1], 16;" :: "r"(dst), "l"(src));
}
__device__ __forceinline__ void cp_commit() { asm volatile("cp.async.commit_group;"); }
template<int N> __device__ __forceinline__ void cp_wait() {
    asm volatile("cp.async.wait_group %0;" :: "n"(N));
}

// ---------------------------------------------------------------------------
// prep kernel: wcvt (blocks 0..4095), emb (4096..4607), ln (4608..12799)
// All three are independent; merged to cut launch overhead.
// ---------------------------------------------------------------------------
__global__ __launch_bounds__(256) void prep_kernel(const float* __restrict__ qw,
                                                   const float* __restrict__ kw,
                                                   const float* __restrict__ vw,
                                                   const float* __restrict__ ow,
                                                   const float* __restrict__ x,
                                                   const float* __restrict__ gam,
                                                   const float* __restrict__ bet) {
    const int bx = blockIdx.x;
    if (bx < 4096) {
        // weight convert: 4 matrices x 1024 blocks
        const int which = bx >> 10;
        const int blk = bx & 1023;
        const float* src = (which == 0) ? qw : (which == 1) ? kw : (which == 2) ? vw : ow;
        __nv_bfloat16* dst = (which == 0) ? g_wq : (which == 1) ? g_wk
                            : (which == 2) ? g_wv : g_wo;
        int i = (blk * 256 + threadIdx.x) * 4;
        float4 v = *(const float4*)(src + i);
        uint2 o;
        o.x = pack_bf16(v.x, v.y);
        o.y = pack_bf16(v.z, v.w);
        *(uint2*)(dst + i) = o;
        return;
    }
    if (bx < 4608) {
        int idx = (bx - 4096) * 256 + threadIdx.x;
        if (idx < SEQ * HD) {
            int s = idx / HD, d = idx % HD;
            int i = d & 31;
            double invf = exp(-((double)(2 * i) / 64.0) * log(10000.0));
            double ang = (double)s * invf;
            g_emb[idx] = (float)((d < 32) ? sin(ang) : cos(ang));
        }
        return;
    }
    // LayerNorm: one block per row
    int row = bx - 4608;
    const float4* xr = (const float4*)(x + (size_t)row * D_MODEL);
    float4 v = xr[threadIdx.x];
    float sum = v.x + v.y + v.z + v.w;
    float sq  = v.x*v.x + v.y*v.y + v.z*v.z + v.w*v.w;
    #pragma unroll
    for (int o = 16; o; o >>= 1) {
        sum += __shfl_xor_sync(0xFFFFFFFFu, sum, o);
        sq  += __shfl_xor_sync(0xFFFFFFFFu, sq, o);
    }
    __shared__ float ssum[8], ssq[8];
    int w = threadIdx.x >> 5, l = threadIdx.x & 31;
    if (!l) { ssum[w] = sum; ssq[w] = sq; }
    __syncthreads();
    if (w == 0) {
        sum = (l < 8) ? ssum[l] : 0.f;
        sq  = (l < 8) ? ssq[l]  : 0.f;
        #pragma unroll
        for (int o = 4; o; o >>= 1) {
            sum += __shfl_xor_sync(0xFFFFFFFFu, sum, o);
            sq  += __shfl_xor_sync(0xFFFFFFFFu, sq, o);
        }
        if (!l) { ssum[0] = sum; ssq[0] = sq; }
    }
    __syncthreads();
    float mu  = ssum[0] * (1.f / D_MODEL);
    float var = ssq[0] * (1.f / D_MODEL) - mu * mu;
    float rs  = rsqrtf(var + 1e-5f);
    int c = threadIdx.x * 4;
    float4 g4 = *(const float4*)(gam + c);
    float4 b4 = *(const float4*)(bet + c);
    uint2 o;
    o.x = pack_bf16((v.x - mu) * rs * g4.x + b4.x, (v.y - mu) * rs * g4.y + b4.y);
    o.y = pack_bf16((v.z - mu) * rs * g4.z + b4.z, (v.w - mu) * rs * g4.w + b4.w);
    *(uint2*)(g_xln + (size_t)row * D_MODEL + c) = o;
}

// ---------------------------------------------------------------------------
// bf16 GEMM core (R10 config): CTA 128x128, k-stage 64 (16 iters), 3-stage ring.
// ---------------------------------------------------------------------------
struct GemmAcc { float a[4][4][4]; };

__device__ __forceinline__ void gemm_core(const __nv_bfloat16* __restrict__ A,
                                          const __nv_bfloat16* __restrict__ B,
                                          int m0, int n0, GemmAcc& G, char* sm) {
    const int tid  = threadIdx.x;
    const int lane = tid & 31, warp = tid >> 5;
    const int wm = warp >> 2, wn = warp & 3;

    #pragma unroll
    for (int mt = 0; mt < 4; mt++)
        #pragma unroll
        for (int nt = 0; nt < 4; nt++)
            #pragma unroll
            for (int j = 0; j < 4; j++) G.a[mt][nt][j] = 0.f;

    auto issue = [&](int st, int k0) {
        char* As = sm + st * G_STAGE_BYTES;
        char* Bs = As + G_ASIZE;
        #pragma unroll
        for (int t = 0; t < 4; t++) {
            int idx = tid + t * 256;
            int row = idx >> 3;
            int cb  = (idx & 7) * 16;
            cpa16(sptr(As + row * G_PITCHB + cb),
                  (const char*)(A + (size_t)(m0 + row) * D_MODEL + k0) + cb);
            cpa16(sptr(Bs + row * G_PITCHB + cb),
                  (const char*)(B + (size_t)(n0 + row) * D_MODEL + k0) + cb);
        }
        cp_commit();
    };

    issue(0, 0);
    issue(1, 64);

    const int arow = (lane & 15);
    const int ahi  = (lane >> 4) * 16;
    const int brow = ((lane >> 4) & 1) * 8 + (lane & 7);
    const int bhi  = ((lane >> 3) & 1) * 16;

    for (int kt = 0; kt < 16; kt++) {
        const int st = kt - (kt / 3) * 3;
        if (kt < 15) cp_wait<1>(); else cp_wait<0>();
        __syncthreads();
        if (kt + 2 < 16) issue((kt + 2) - ((kt + 2) / 3) * 3, (kt + 2) * 64);

        char* As = sm + st * G_STAGE_BYTES;
        char* Bs = As + G_ASIZE;
        #pragma unroll
        for (int ks = 0; ks < 4; ks++) {
            const int kkB = ks * 32;
            uint32_t af[4][4];
            #pragma unroll
            for (int mt = 0; mt < 4; mt++)
                ldsm4(af[mt][0], af[mt][1], af[mt][2], af[mt][3],
                      sptr(As + (wm * 64 + mt * 16 + arow) * G_PITCHB + kkB + ahi));
            uint32_t bf[4][2];
            #pragma unroll
            for (int np = 0; np < 2; np++) {
                uint32_t t0, t1, t2, t3;
                ldsm4(t0, t1, t2, t3,
                      sptr(Bs + (wn * 32 + np * 16 + brow) * G_PITCHB + kkB + bhi));
                bf[np * 2][0] = t0;     bf[np * 2][1] = t1;
                bf[np * 2 + 1][0] = t2; bf[np * 2 + 1][1] = t3;
            }
            #pragma unroll
            for (int mt = 0; mt < 4; mt++)
                #pragma unroll
                for (int nt = 0; nt < 4; nt++)
                    mma16(G.a[mt][nt], af[mt], bf[nt][0], bf[nt][1]);
        }
    }
}

// ---------------------------------------------------------------------------
// QKV proj: grid (24, 64). Fused rotary + q scale (0.125*log2e) + head-split.
// ---------------------------------------------------------------------------
__global__ __launch_bounds__(256, 2) void gemm_qkv() {
    extern __shared__ char dynsm_g[];
    const int m0 = blockIdx.y * 128;
    const int which = blockIdx.x >> 3;
    const int n0 = (blockIdx.x & 7) * 128;
    const __nv_bfloat16* W = (which == 0) ? g_wq : (which == 1) ? g_wk : g_wv;

    GemmAcc G;
    gemm_core(g_xln, W, m0, n0, G, dynsm_g);

    const int lane = threadIdx.x & 31, warp = threadIdx.x >> 5;
    const int wm = warp >> 2, wn = warp & 3;
    __nv_bfloat16* dst = (which == 0) ? g_q : (which == 1) ? g_k : g_v;
    const float qscale = 0.125f * 1.4426950408889634f;

    #pragma unroll
    for (int mt = 0; mt < 4; mt++) {
        #pragma unroll
        for (int rh = 0; rh < 2; rh++) {
            int m = m0 + wm * 64 + mt * 16 + rh * 8 + (lane >> 2);
            int b = m >> 11, s = m & 2047;
            #pragma unroll
            for (int nt = 0; nt < 4; nt++) {
                int n  = n0 + wn * 32 + nt * 8 + (lane & 3) * 2;
                int h  = n >> 6, dc = n & 63;
                float ex = 1.f, ey = 1.f;
                if (which < 2) {
                    float2 e = *(const float2*)&g_emb[s * HD + dc];
                    ex = e.x; ey = e.y;
                    if (which == 0) { ex *= qscale; ey *= qscale; }
                }
                uint32_t o = pack_bf16(G.a[mt][nt][rh * 2 + 0] * ex,
                                       G.a[mt][nt][rh * 2 + 1] * ey);
                *(uint32_t*)&dst[((size_t)(b * NHEAD + h) * SEQ + s) * HD + dc] = o;
            }
        }
    }
}

// ---------------------------------------------------------------------------
// out proj + bias + residual (R10 config): grid (8, 64)
// ---------------------------------------------------------------------------
__global__ __launch_bounds__(256, 2) void gemm_out(const float* __restrict__ ob,
                                                   const float* __restrict__ x,
                                                   float* __restrict__ out) {
    extern __shared__ char dynsm_o[];
    const int m0 = blockIdx.y * 128;
    const int n0 = blockIdx.x * 128;

    GemmAcc G;
    gemm_core(g_ctx, g_wo, m0, n0, G, dynsm_o);

    const int lane = threadIdx.x & 31, warp = threadIdx.x >> 5;
    const int wm = warp >> 2, wn = warp & 3;

    #pragma unroll
    for (int mt = 0; mt < 4; mt++) {
        #pragma unroll
        for (int rh = 0; rh < 2; rh++) {
            int m = m0 + wm * 64 + mt * 16 + rh * 8 + (lane >> 2);
            #pragma unroll
            for (int nt = 0; nt < 4; nt++) {
                int n = n0 + wn * 32 + nt * 8 + (lane & 3) * 2;
                float2 bb = *(const float2*)&ob[n];
                float2 xx = *(const float2*)&x[(size_t)m * D_MODEL + n];
                float2 o;
                o.x = G.a[mt][nt][rh * 2 + 0] + bb.x + xx.x;
                o.y = G.a[mt][nt][rh * 2 + 1] + bb.y + xx.y;
                *(float2*)&out[(size_t)m * D_MODEL + n] = o;
            }
        }
    }
}

// ---------------------------------------------------------------------------
// Flash attention (R10 + smem-staged mask). grid (8, 64).
// ---------------------------------------------------------------------------
__global__ __launch_bounds__(256, 2) void attn_kernel(const unsigned char* __restrict__ kpm) {
    extern __shared__ char dynsm_a[];

    const int tid = threadIdx.x, lane = tid & 31, warp = tid >> 5;
    const int bh = blockIdx.y;
    const int batch = bh >> 4, h = bh & 15;

    const __nv_bfloat16* __restrict__ Qg = g_q + (size_t)bh * SEQ * HD;
    const __nv_bfloat16* __restrict__ Kg = g_k + (size_t)bh * SEQ * HD;
    const __nv_bfloat16* __restrict__ Vg = g_v + (size_t)bh * SEQ * HD;
    const unsigned char* __restrict__ maskg = kpm + (size_t)batch * SEQ;
    unsigned char* smask = (unsigned char*)(dynsm_a + A_MASK_OFF);

    auto stageK = [&](int st) { return dynsm_a + st * A_STAGE_BYTES; };
    auto stageV = [&](int st) { return dynsm_a + st * A_STAGE_BYTES + A_HALF; };

    auto issue = [&](int st, int kbase) {
        char* Ks = stageK(st);
        char* Vs = stageV(st);
        #pragma unroll
        for (int t = 0; t < 4; t++) {
            int idx = tid + t * 256;
            int row = idx >> 3;
            int cb  = (idx & 7) * 16;
            cpa16(sptr(Ks + row * G_PITCHB + cb),
                  (const char*)(Kg + (size_t)(kbase + row) * HD) + cb);
            cpa16(sptr(Vs + row * G_PITCHB + cb),
                  (const char*)(Vg + (size_t)(kbase + row) * HD) + cb);
        }
        cp_commit();
    };

    // stage full mask once (2048 B, 8 B per thread)
    *(uint2*)(smask + tid * 8) = *(const uint2*)(maskg + tid * 8);

    const int brow = ((lane >> 4) & 1) * 8 + (lane & 7);
    const int bhi  = ((lane >> 3) & 1) * 16;
    const int vrow = ((lane >> 3) & 1) * 8 + (lane & 7);
    const int vhi  = (lane >> 4) * 16;

    #pragma unroll 1
    for (int ph = 0; ph < 2; ph++) {
        const int qb = ph ? (15 - blockIdx.x) : blockIdx.x;
        const int q0 = qb * 128;
        const int nkb = qb + 1;

        __syncthreads();          // ring reuse + (ph0) mask visibility
        issue(0, 0);
        if (nkb > 1) issue(1, 128);

        uint32_t qf[4][4];
        {
            const int r0 = q0 + warp * 16 + (lane >> 2);
            #pragma unroll
            for (int t = 0; t < 4; t++) {
                int c = t * 16 + (lane & 3) * 2;
                qf[t][0] = *(const uint32_t*)&Qg[(size_t)r0 * HD + c];
                qf[t][1] = *(const uint32_t*)&Qg[(size_t)(r0 + 8) * HD + c];
                qf[t][2] = *(const uint32_t*)&Qg[(size_t)r0 * HD + c + 8];
                qf[t][3] = *(const uint32_t*)&Qg[(size_t)(r0 + 8) * HD + c + 8];
            }
        }

        float o[8][4];
        #pragma unroll
        for (int nt = 0; nt < 8; nt++)
            #pragma unroll
            for (int j = 0; j < 4; j++) o[nt][j] = 0.f;
        float mi0 = -INFINITY, mi1 = -INFINITY, li0 = 0.f, li1 = 0.f;

        #pragma unroll 1
        for (int kb = 0; kb < nkb; kb++) {
            const int st = kb - (kb / 3) * 3;
            if (kb + 1 < nkb) cp_wait<1>(); else cp_wait<0>();
            __syncthreads();
            if (kb + 2 < nkb) issue((kb + 2) - ((kb + 2) / 3) * 3, (kb + 2) * 128);

            const char* Ks = stageK(st);
            const char* Vs = stageV(st);

            #pragma unroll 1
            for (int sub = 0; sub < 2; sub++) {
                const int kbase = kb * 128 + sub * 64;
                const int srow  = sub * 64;
                const bool active = (kbase <= q0 + warp * 16 + 15);
                if (!active) continue;

                float s[8][4];
                #pragma unroll
                for (int nt = 0; nt < 8; nt++)
                    #pragma unroll
                    for (int j = 0; j < 4; j++) s[nt][j] = 0.f;
                #pragma unroll
                for (int ks = 0; ks < 4; ks++) {
                    #pragma unroll
                    for (int np = 0; np < 4; np++) {
                        uint32_t t0, t1, t2, t3;
                        ldsm4(t0, t1, t2, t3,
                              sptr(Ks + (srow + np * 16 + brow) * G_PITCHB + ks * 32 + bhi));
                        mma16(s[np * 2], qf[ks], t0, t1);
                        mma16(s[np * 2 + 1], qf[ks], t2, t3);
                    }
                }

                const int row0 = q0 + warp * 16 + (lane >> 2);
                const bool needc = (kbase + 63) > (q0 + warp * 16);
                #pragma unroll
                for (int nt = 0; nt < 8; nt++) {
                    int c = nt * 8 + (lane & 3) * 2;
                    unsigned char mb0 = smask[kbase + c], mb1 = smask[kbase + c + 1];
                    if (mb0) { s[nt][0] = -INFINITY; s[nt][2] = -INFINITY; }
                    if (mb1) { s[nt][1] = -INFINITY; s[nt][3] = -INFINITY; }
                    if (needc) {
                        int cg = kbase + c;
                        if (cg     > row0)     s[nt][0] = -INFINITY;
                        if (cg + 1 > row0)     s[nt][1] = -INFINITY;
                        if (cg     > row0 + 8) s[nt][2] = -INFINITY;
                        if (cg + 1 > row0 + 8) s[nt][3] = -INFINITY;
                    }
                }

                float mx0 = -INFINITY, mx1 = -INFINITY;
                #pragma unroll
                for (int nt = 0; nt < 8; nt++) {
                    mx0 = fmaxf(mx0, fmaxf(s[nt][0], s[nt][1]));
                    mx1 = fmaxf(mx1, fmaxf(s[nt][2], s[nt][3]));
                }
                mx0 = fmaxf(mx0, __shfl_xor_sync(0xFFFFFFFFu, mx0, 1));
                mx0 = fmaxf(mx0, __shfl_xor_sync(0xFFFFFFFFu, mx0, 2));
                mx1 = fmaxf(mx1, __shfl_xor_sync(0xFFFFFFFFu, mx1, 1));
                mx1 = fmaxf(mx1, __shfl_xor_sync(0xFFFFFFFFu, mx1, 2));
                float mt0 = fmaxf(mi0, mx0), mt1 = fmaxf(mi1, mx1);
                float ms0 = (mt0 == -INFINITY) ? 0.f : mt0;
                float ms1 = (mt1 == -INFINITY) ? 0.f : mt1;
                float al0 = exp2f(mi0 - ms0), al1 = exp2f(mi1 - ms1);
                mi0 = mt0; mi1 = mt1;
                float rs0 = 0.f, rs1 = 0.f;
                #pragma unroll
                for (int nt = 0; nt < 8; nt++) {
                    s[nt][0] = exp2f(s[nt][0] - ms0); rs0 += s[nt][0];
                    s[nt][1] = exp2f(s[nt][1] - ms0); rs0 += s[nt][1];
                    s[nt][2] = exp2f(s[nt][2] - ms1); rs1 += s[nt][2];
                    s[nt][3] = exp2f(s[nt][3] - ms1); rs1 += s[nt][3];
                }
                rs0 += __shfl_xor_sync(0xFFFFFFFFu, rs0, 1);
                rs0 += __shfl_xor_sync(0xFFFFFFFFu, rs0, 2);
                rs1 += __shfl_xor_sync(0xFFFFFFFFu, rs1, 1);
                rs1 += __shfl_xor_sync(0xFFFFFFFFu, rs1, 2);
                li0 = li0 * al0 + rs0;
                li1 = li1 * al1 + rs1;
                #pragma unroll
                for (int nt = 0; nt < 8; nt++) {
                    o[nt][0] *= al0; o[nt][1] *= al0;
                    o[nt][2] *= al1; o[nt][3] *= al1;
                }

                #pragma unroll
                for (int t = 0; t < 4; t++) {
                    uint32_t pa[4];
                    pa[0] = pack_bf16(s[2 * t][0],     s[2 * t][1]);
                    pa[1] = pack_bf16(s[2 * t][2],     s[2 * t][3]);
                    pa[2] = pack_bf16(s[2 * t + 1][0], s[2 * t + 1][1]);
                    pa[3] = pack_bf16(s[2 * t + 1][2], s[2 * t + 1][3]);
                    #pragma unroll
                    for (int np = 0; np < 4; np++) {
                        uint32_t t0, t1, t2, t3;
                        ldsm4t(t0, t1, t2, t3,
                               sptr(Vs + (srow + t * 16 + vrow) * G_PITCHB + np * 32 + vhi));
                        mma16(o[np * 2], pa, t0, t1);
                        mma16(o[np * 2 + 1], pa, t2, t3);
                    }
                }
            }
        }

        const float inv0 = 1.f / li0, inv1 = 1.f / li1;
        const int r0 = q0 + warp * 16 + (lane >> 2);
        #pragma unroll
        for (int nt = 0; nt < 8; nt++) {
            int dc = nt * 8 + (lane & 3) * 2;
            uint32_t w0 = pack_bf16(o[nt][0] * inv0, o[nt][1] * inv0);
            uint32_t w1 = pack_bf16(o[nt][2] * inv1, o[nt][3] * inv1);
            *(uint32_t*)&g_ctx[(size_t)(batch * SEQ + r0) * D_MODEL + h * HD + dc] = w0;
            *(uint32_t*)&g_ctx[(size_t)(batch * SEQ + r0 + 8) * D_MODEL + h * HD + dc] = w1;
        }
    }
}

// ---------------------------------------------------------------------------
extern "C" void kernel_launch(void* const* d_in, const int* in_sizes, int n_in,
                              void* d_out, int out_size) {
    const float* x  = (const float*)d_in[0];
    const unsigned char* kpm = (const unsigned char*)d_in[1];
    const float* qw = (const float*)d_in[2];
    const float* kw = (const float*)d_in[3];
    const float* vw = (const float*)d_in[4];
    const float* ow = (const float*)d_in[5];
    const float* ob = (const float*)d_in[6];
    const float* lg = (const float*)d_in[7];
    const float* lb = (const float*)d_in[8];
    float* out = (float*)d_out;

    static bool attr_done = false;
    if (!attr_done) {
        cudaFuncSetAttribute(gemm_qkv, cudaFuncAttributeMaxDynamicSharedMemorySize, G_SMEM_BYTES);
        cudaFuncSetAttribute(gemm_out, cudaFuncAttributeMaxDynamicSharedMemorySize, G_SMEM_BYTES);
        cudaFuncSetAttribute(attn_kernel, cudaFuncAttributeMaxDynamicSharedMemorySize, A_SMEM_BYTES);
        attr_done = true;
    }

    prep_kernel<<<12800, 256>>>(qw, kw, vw, ow, x, lg, lb);
    gemm_qkv<<<dim3(24, 64), 256, G_SMEM_BYTES>>>();
    attn_kernel<<<dim3(8, 64), 256, A_SMEM_BYTES>>>(kpm);
    gemm_out<<<dim3(8, 64), 256, G_SMEM_BYTES>>>(ob, x, out);
}

// round 14
// speedup vs baseline: 1.1257x; 1.0460x over previous
#include <cuda_runtime.h>
#include <cuda_bf16.h>
#include <cstdint>
#include <math.h>

#define D_MODEL 1024
#define NHEAD   16
#define HD      64
#define SEQ     2048
#define BATCH   4
#define MTOT    (BATCH*SEQ)      // 8192
#define BHN     (BATCH*NHEAD)    // 64

static __device__ __nv_bfloat16 g_xln[MTOT * D_MODEL];
static __device__ __nv_bfloat16 g_q[BHN * SEQ * HD];
static __device__ __nv_bfloat16 g_k[BHN * SEQ * HD];
static __device__ __nv_bfloat16 g_v[BHN * SEQ * HD];
static __device__ __nv_bfloat16 g_ctx[MTOT * D_MODEL];
static __device__ __nv_bfloat16 g_wq[D_MODEL * D_MODEL];
static __device__ __nv_bfloat16 g_wk[D_MODEL * D_MODEL];
static __device__ __nv_bfloat16 g_wv[D_MODEL * D_MODEL];
static __device__ __nv_bfloat16 g_wo[D_MODEL * D_MODEL];
static __device__ float g_emb[SEQ * HD];

// GEMM smem: 3 stages x (A[128] + B[128]) rows of 72 bf16 (144B pitch)
#define G_PITCHB  144
#define G_ASIZE   (128 * G_PITCHB)          // 18432
#define G_STAGE_BYTES (2 * G_ASIZE)          // 36864
#define G_SMEM_BYTES  (3 * G_STAGE_BYTES)    // 110592
// attn smem: 3 stages x (K[128][72] + V[128][72]) + mask[2048] + flags[32]
#define A_KROWS   128
#define A_HALF    (A_KROWS * G_PITCHB)       // 18432
#define A_STAGE_BYTES (2 * A_HALF)           // 36864
#define A_MASK_OFF (3 * A_STAGE_BYTES)       // 110592
#define A_FLAG_OFF (A_MASK_OFF + 2048)       // 112640
#define A_SMEM_BYTES  (A_FLAG_OFF + 32)      // 112672

// ---------------------------------------------------------------------------
// helpers
// ---------------------------------------------------------------------------
__device__ __forceinline__ uint32_t sptr(const void* p) {
    return (uint32_t)__cvta_generic_to_shared(p);
}
__device__ __forceinline__ uint32_t pack_bf16(float lo, float hi) {
    uint32_t d;
    asm("cvt.rn.bf16x2.f32 %0, %1, %2;" : "=r"(d) : "f"(hi), "f"(lo));
    return d;
}
__device__ __forceinline__ void ldsm4(uint32_t& r0, uint32_t& r1, uint32_t& r2, uint32_t& r3,
                                      uint32_t addr) {
    asm volatile("ldmatrix.sync.aligned.m8n8.x4.shared.b16 {%0,%1,%2,%3}, [%4];"
                 : "=r"(r0), "=r"(r1), "=r"(r2), "=r"(r3) : "r"(addr));
}
__device__ __forceinline__ void ldsm4t(uint32_t& r0, uint32_t& r1, uint32_t& r2, uint32_t& r3,
                                       uint32_t addr) {
    asm volatile("ldmatrix.sync.aligned.m8n8.x4.trans.shared.b16 {%0,%1,%2,%3}, [%4];"
                 : "=r"(r0), "=r"(r1), "=r"(r2), "=r"(r3) : "r"(addr));
}
__device__ __forceinline__ void mma16(float* c, const uint32_t* a, uint32_t b0, uint32_t b1) {
    asm volatile("mma.sync.aligned.m16n8k16.row.col.f32.bf16.bf16.f32 "
                 "{%0,%1,%2,%3}, {%4,%5,%6,%7}, {%8,%9}, {%0,%1,%2,%3};"
                 : "+f"(c[0]), "+f"(c[1]), "+f"(c[2]), "+f"(c[3])
                 : "r"(a[0]), "r"(a[1]), "r"(a[2]), "r"(a[3]), "r"(b0), "r"(b1));
}
__device__ __forceinline__ void cpa16(uint32_t dst, const void* src) {
    asm volatile("cp.async.cg.shared.global [%0], [%1], 16;" :: "r"(dst), "l"(src));
}
__device__ __forceinline__ void cp_commit() { asm volatile("cp.async.commit_group;"); }
template<int N> __device__ __forceinline__ void cp_wait() {
    asm volatile("cp.async.wait_group %0;" :: "n"(N));
}

// ---------------------------------------------------------------------------
// prep kernel: wcvt (blocks 0..4095), emb (4096..4607), ln (4608..12799)
// ---------------------------------------------------------------------------
__global__ __launch_bounds__(256) void prep_kernel(const float* __restrict__ qw,
                                                   const float* __restrict__ kw,
                                                   const float* __restrict__ vw,
                                                   const float* __restrict__ ow,
                                                   const float* __restrict__ x,
                                                   const float* __restrict__ gam,
                                                   const float* __restrict__ bet) {
    const int bx = blockIdx.x;
    if (bx < 4096) {
        const int which = bx >> 10;
        const int blk = bx & 1023;
        const float* src = (which == 0) ? qw : (which == 1) ? kw : (which == 2) ? vw : ow;
        __nv_bfloat16* dst = (which == 0) ? g_wq : (which == 1) ? g_wk
                            : (which == 2) ? g_wv : g_wo;
        int i = (blk * 256 + threadIdx.x) * 4;
        float4 v = *(const float4*)(src + i);
        uint2 o;
        o.x = pack_bf16(v.x, v.y);
        o.y = pack_bf16(v.z, v.w);
        *(uint2*)(dst + i) = o;
        return;
    }
    if (bx < 4608) {
        int idx = (bx - 4096) * 256 + threadIdx.x;
        if (idx < SEQ * HD) {
            int s = idx / HD, d = idx % HD;
            int i = d & 31;
            double invf = exp(-((double)(2 * i) / 64.0) * log(10000.0));
            double ang = (double)s * invf;
            g_emb[idx] = (float)((d < 32) ? sin(ang) : cos(ang));
        }
        return;
    }
    int row = bx - 4608;
    const float4* xr = (const float4*)(x + (size_t)row * D_MODEL);
    float4 v = xr[threadIdx.x];
    float sum = v.x + v.y + v.z + v.w;
    float sq  = v.x*v.x + v.y*v.y + v.z*v.z + v.w*v.w;
    #pragma unroll
    for (int o = 16; o; o >>= 1) {
        sum += __shfl_xor_sync(0xFFFFFFFFu, sum, o);
        sq  += __shfl_xor_sync(0xFFFFFFFFu, sq, o);
    }
    __shared__ float ssum[8], ssq[8];
    int w = threadIdx.x >> 5, l = threadIdx.x & 31;
    if (!l) { ssum[w] = sum; ssq[w] = sq; }
    __syncthreads();
    if (w == 0) {
        sum = (l < 8) ? ssum[l] : 0.f;
        sq  = (l < 8) ? ssq[l]  : 0.f;
        #pragma unroll
        for (int o = 4; o; o >>= 1) {
            sum += __shfl_xor_sync(0xFFFFFFFFu, sum, o);
            sq  += __shfl_xor_sync(0xFFFFFFFFu, sq, o);
        }
        if (!l) { ssum[0] = sum; ssq[0] = sq; }
    }
    __syncthreads();
    float mu  = ssum[0] * (1.f / D_MODEL);
    float var = ssq[0] * (1.f / D_MODEL) - mu * mu;
    float rs  = rsqrtf(var + 1e-5f);
    int c = threadIdx.x * 4;
    float4 g4 = *(const float4*)(gam + c);
    float4 b4 = *(const float4*)(bet + c);
    uint2 o;
    o.x = pack_bf16((v.x - mu) * rs * g4.x + b4.x, (v.y - mu) * rs * g4.y + b4.y);
    o.y = pack_bf16((v.z - mu) * rs * g4.z + b4.z, (v.w - mu) * rs * g4.w + b4.w);
    *(uint2*)(g_xln + (size_t)row * D_MODEL + c) = o;
}

// ---------------------------------------------------------------------------
// bf16 GEMM core (R10 config): CTA 128x128, k-stage 64 (16 iters), 3-stage ring.
// ---------------------------------------------------------------------------
struct GemmAcc { float a[4][4][4]; };

__device__ __forceinline__ void gemm_core(const __nv_bfloat16* __restrict__ A,
                                          const __nv_bfloat16* __restrict__ B,
                                          int m0, int n0, GemmAcc& G, char* sm) {
    const int tid  = threadIdx.x;
    const int lane = tid & 31, warp = tid >> 5;
    const int wm = warp >> 2, wn = warp & 3;

    #pragma unroll
    for (int mt = 0; mt < 4; mt++)
        #pragma unroll
        for (int nt = 0; nt < 4; nt++)
            #pragma unroll
            for (int j = 0; j < 4; j++) G.a[mt][nt][j] = 0.f;

    auto issue = [&](int st, int k0) {
        char* As = sm + st * G_STAGE_BYTES;
        char* Bs = As + G_ASIZE;
        #pragma unroll
        for (int t = 0; t < 4; t++) {
            int idx = tid + t * 256;
            int row = idx >> 3;
            int cb  = (idx & 7) * 16;
            cpa16(sptr(As + row * G_PITCHB + cb),
                  (const char*)(A + (size_t)(m0 + row) * D_MODEL + k0) + cb);
            cpa16(sptr(Bs + row * G_PITCHB + cb),
                  (const char*)(B + (size_t)(n0 + row) * D_MODEL + k0) + cb);
        }
        cp_commit();
    };

    issue(0, 0);
    issue(1, 64);

    const int arow = (lane & 15);
    const int ahi  = (lane >> 4) * 16;
    const int brow = ((lane >> 4) & 1) * 8 + (lane & 7);
    const int bhi  = ((lane >> 3) & 1) * 16;

    for (int kt = 0; kt < 16; kt++) {
        const int st = kt - (kt / 3) * 3;
        if (kt < 15) cp_wait<1>(); else cp_wait<0>();
        __syncthreads();
        if (kt + 2 < 16) issue((kt + 2) - ((kt + 2) / 3) * 3, (kt + 2) * 64);

        char* As = sm + st * G_STAGE_BYTES;
        char* Bs = As + G_ASIZE;
        #pragma unroll
        for (int ks = 0; ks < 4; ks++) {
            const int kkB = ks * 32;
            uint32_t af[4][4];
            #pragma unroll
            for (int mt = 0; mt < 4; mt++)
                ldsm4(af[mt][0], af[mt][1], af[mt][2], af[mt][3],
                      sptr(As + (wm * 64 + mt * 16 + arow) * G_PITCHB + kkB + ahi));
            uint32_t bf[4][2];
            #pragma unroll
            for (int np = 0; np < 2; np++) {
                uint32_t t0, t1, t2, t3;
                ldsm4(t0, t1, t2, t3,
                      sptr(Bs + (wn * 32 + np * 16 + brow) * G_PITCHB + kkB + bhi));
                bf[np * 2][0] = t0;     bf[np * 2][1] = t1;
                bf[np * 2 + 1][0] = t2; bf[np * 2 + 1][1] = t3;
            }
            #pragma unroll
            for (int mt = 0; mt < 4; mt++)
                #pragma unroll
                for (int nt = 0; nt < 4; nt++)
                    mma16(G.a[mt][nt], af[mt], bf[nt][0], bf[nt][1]);
        }
    }
}

// ---------------------------------------------------------------------------
// QKV proj: grid (24, 64). Fused rotary + q scale (0.125*log2e) + head-split.
// ---------------------------------------------------------------------------
__global__ __launch_bounds__(256, 2) void gemm_qkv() {
    extern __shared__ char dynsm_g[];
    const int m0 = blockIdx.y * 128;
    const int which = blockIdx.x >> 3;
    const int n0 = (blockIdx.x & 7) * 128;
    const __nv_bfloat16* W = (which == 0) ? g_wq : (which == 1) ? g_wk : g_wv;

    GemmAcc G;
    gemm_core(g_xln, W, m0, n0, G, dynsm_g);

    const int lane = threadIdx.x & 31, warp = threadIdx.x >> 5;
    const int wm = warp >> 2, wn = warp & 3;
    __nv_bfloat16* dst = (which == 0) ? g_q : (which == 1) ? g_k : g_v;
    const float qscale = 0.125f * 1.4426950408889634f;

    #pragma unroll
    for (int mt = 0; mt < 4; mt++) {
        #pragma unroll
        for (int rh = 0; rh < 2; rh++) {
            int m = m0 + wm * 64 + mt * 16 + rh * 8 + (lane >> 2);
            int b = m >> 11, s = m & 2047;
            #pragma unroll
            for (int nt = 0; nt < 4; nt++) {
                int n  = n0 + wn * 32 + nt * 8 + (lane & 3) * 2;
                int h  = n >> 6, dc = n & 63;
                float ex = 1.f, ey = 1.f;
                if (which < 2) {
                    float2 e = *(const float2*)&g_emb[s * HD + dc];
                    ex = e.x; ey = e.y;
                    if (which == 0) { ex *= qscale; ey *= qscale; }
                }
                uint32_t o = pack_bf16(G.a[mt][nt][rh * 2 + 0] * ex,
                                       G.a[mt][nt][rh * 2 + 1] * ey);
                *(uint32_t*)&dst[((size_t)(b * NHEAD + h) * SEQ + s) * HD + dc] = o;
            }
        }
    }
}

// ---------------------------------------------------------------------------
// out proj + bias + residual (R10 config): grid (8, 64)
// ---------------------------------------------------------------------------
__global__ __launch_bounds__(256, 2) void gemm_out(const float* __restrict__ ob,
                                                   const float* __restrict__ x,
                                                   float* __restrict__ out) {
    extern __shared__ char dynsm_o[];
    const int m0 = blockIdx.y * 128;
    const int n0 = blockIdx.x * 128;

    GemmAcc G;
    gemm_core(g_ctx, g_wo, m0, n0, G, dynsm_o);

    const int lane = threadIdx.x & 31, warp = threadIdx.x >> 5;
    const int wm = warp >> 2, wn = warp & 3;

    #pragma unroll
    for (int mt = 0; mt < 4; mt++) {
        #pragma unroll
        for (int rh = 0; rh < 2; rh++) {
            int m = m0 + wm * 64 + mt * 16 + rh * 8 + (lane >> 2);
            #pragma unroll
            for (int nt = 0; nt < 4; nt++) {
                int n = n0 + wn * 32 + nt * 8 + (lane & 3) * 2;
                float2 bb = *(const float2*)&ob[n];
                float2 xx = *(const float2*)&x[(size_t)m * D_MODEL + n];
                float2 o;
                o.x = G.a[mt][nt][rh * 2 + 0] + bb.x + xx.x;
                o.y = G.a[mt][nt][rh * 2 + 1] + bb.y + xx.y;
                *(float2*)&out[(size_t)m * D_MODEL + n] = o;
            }
        }
    }
}

// ---------------------------------------------------------------------------
// Flash attention: R13 + per-64-key-block mask flags (fast path skips all
// mask loads when block is unmasked) + -1e30 max init (no -inf selects).
// ---------------------------------------------------------------------------
__global__ __launch_bounds__(256, 2) void attn_kernel(const unsigned char* __restrict__ kpm) {
    extern __shared__ char dynsm_a[];

    const int tid = threadIdx.x, lane = tid & 31, warp = tid >> 5;
    const int bh = blockIdx.y;
    const int batch = bh >> 4, h = bh & 15;

    const __nv_bfloat16* __restrict__ Qg = g_q + (size_t)bh * SEQ * HD;
    const __nv_bfloat16* __restrict__ Kg = g_k + (size_t)bh * SEQ * HD;
    const __nv_bfloat16* __restrict__ Vg = g_v + (size_t)bh * SEQ * HD;
    const unsigned char* __restrict__ maskg = kpm + (size_t)batch * SEQ;
    unsigned char* smask = (unsigned char*)(dynsm_a + A_MASK_OFF);
    unsigned char* sflag = (unsigned char*)(dynsm_a + A_FLAG_OFF);

    auto stageK = [&](int st) { return dynsm_a + st * A_STAGE_BYTES; };
    auto stageV = [&](int st) { return dynsm_a + st * A_STAGE_BYTES + A_HALF; };

    auto issue = [&](int st, int kbase) {
        char* Ks = stageK(st);
        char* Vs = stageV(st);
        #pragma unroll
        for (int t = 0; t < 4; t++) {
            int idx = tid + t * 256;
            int row = idx >> 3;
            int cb  = (idx & 7) * 16;
            cpa16(sptr(Ks + row * G_PITCHB + cb),
                  (const char*)(Kg + (size_t)(kbase + row) * HD) + cb);
            cpa16(sptr(Vs + row * G_PITCHB + cb),
                  (const char*)(Vg + (size_t)(kbase + row) * HD) + cb);
        }
        cp_commit();
    };

    // stage full mask (2048 B), then per-64-key-block nonzero flags
    *(uint2*)(smask + tid * 8) = *(const uint2*)(maskg + tid * 8);
    __syncthreads();
    if (tid < 32) {
        const uint32_t* mw = (const uint32_t*)(smask + tid * 64);
        uint32_t acc = 0;
        #pragma unroll
        for (int i = 0; i < 16; i++) acc |= mw[i];
        sflag[tid] = acc ? 1 : 0;
    }

    const int brow = ((lane >> 4) & 1) * 8 + (lane & 7);
    const int bhi  = ((lane >> 3) & 1) * 16;
    const int vrow = ((lane >> 3) & 1) * 8 + (lane & 7);
    const int vhi  = (lane >> 4) * 16;

    #pragma unroll 1
    for (int ph = 0; ph < 2; ph++) {
        const int qb = ph ? (15 - blockIdx.x) : blockIdx.x;
        const int q0 = qb * 128;
        const int nkb = qb + 1;

        __syncthreads();          // ring reuse + flag visibility
        issue(0, 0);
        if (nkb > 1) issue(1, 128);

        uint32_t qf[4][4];
        {
            const int r0 = q0 + warp * 16 + (lane >> 2);
            #pragma unroll
            for (int t = 0; t < 4; t++) {
                int c = t * 16 + (lane & 3) * 2;
                qf[t][0] = *(const uint32_t*)&Qg[(size_t)r0 * HD + c];
                qf[t][1] = *(const uint32_t*)&Qg[(size_t)(r0 + 8) * HD + c];
                qf[t][2] = *(const uint32_t*)&Qg[(size_t)r0 * HD + c + 8];
                qf[t][3] = *(const uint32_t*)&Qg[(size_t)(r0 + 8) * HD + c + 8];
            }
        }

        float o[8][4];
        #pragma unroll
        for (int nt = 0; nt < 8; nt++)
            #pragma unroll
            for (int j = 0; j < 4; j++) o[nt][j] = 0.f;
        float mi0 = -1e30f, mi1 = -1e30f, li0 = 0.f, li1 = 0.f;

        #pragma unroll 1
        for (int kb = 0; kb < nkb; kb++) {
            const int st = kb - (kb / 3) * 3;
            if (kb + 1 < nkb) cp_wait<1>(); else cp_wait<0>();
            __syncthreads();
            if (kb + 2 < nkb) issue((kb + 2) - ((kb + 2) / 3) * 3, (kb + 2) * 128);

            const char* Ks = stageK(st);
            const char* Vs = stageV(st);

            #pragma unroll 1
            for (int sub = 0; sub < 2; sub++) {
                const int kbase = kb * 128 + sub * 64;
                const int srow  = sub * 64;
                const bool active = (kbase <= q0 + warp * 16 + 15);
                if (!active) continue;

                float s[8][4];
                #pragma unroll
                for (int nt = 0; nt < 8; nt++)
                    #pragma unroll
                    for (int j = 0; j < 4; j++) s[nt][j] = 0.f;
                #pragma unroll
                for (int ks = 0; ks < 4; ks++) {
                    #pragma unroll
                    for (int np = 0; np < 4; np++) {
                        uint32_t t0, t1, t2, t3;
                        ldsm4(t0, t1, t2, t3,
                              sptr(Ks + (srow + np * 16 + brow) * G_PITCHB + ks * 32 + bhi));
                        mma16(s[np * 2], qf[ks], t0, t1);
                        mma16(s[np * 2 + 1], qf[ks], t2, t3);
                    }
                }

                // padding mask: only when this 64-key block has any masked keys
                if (sflag[kbase >> 6]) {
                    #pragma unroll
                    for (int nt = 0; nt < 8; nt++) {
                        int c = nt * 8 + (lane & 3) * 2;
                        unsigned char mb0 = smask[kbase + c], mb1 = smask[kbase + c + 1];
                        if (mb0) { s[nt][0] = -INFINITY; s[nt][2] = -INFINITY; }
                        if (mb1) { s[nt][1] = -INFINITY; s[nt][3] = -INFINITY; }
                    }
                }
                // causal mask (diagonal block only)
                const int row0 = q0 + warp * 16 + (lane >> 2);
                if ((kbase + 63) > (q0 + warp * 16)) {
                    #pragma unroll
                    for (int nt = 0; nt < 8; nt++) {
                        int cg = kbase + nt * 8 + (lane & 3) * 2;
                        if (cg     > row0)     s[nt][0] = -INFINITY;
                        if (cg + 1 > row0)     s[nt][1] = -INFINITY;
                        if (cg     > row0 + 8) s[nt][2] = -INFINITY;
                        if (cg + 1 > row0 + 8) s[nt][3] = -INFINITY;
                    }
                }

                float mx0 = -1e30f, mx1 = -1e30f;
                #pragma unroll
                for (int nt = 0; nt < 8; nt++) {
                    mx0 = fmaxf(mx0, fmaxf(s[nt][0], s[nt][1]));
                    mx1 = fmaxf(mx1, fmaxf(s[nt][2], s[nt][3]));
                }
                mx0 = fmaxf(mx0, __shfl_xor_sync(0xFFFFFFFFu, mx0, 1));
                mx0 = fmaxf(mx0, __shfl_xor_sync(0xFFFFFFFFu, mx0, 2));
                mx1 = fmaxf(mx1, __shfl_xor_sync(0xFFFFFFFFu, mx1, 1));
                mx1 = fmaxf(mx1, __shfl_xor_sync(0xFFFFFFFFu, mx1, 2));
                float mt0 = fmaxf(mi0, mx0), mt1 = fmaxf(mi1, mx1);
                float al0 = exp2f(mi0 - mt0), al1 = exp2f(mi1 - mt1);
                mi0 = mt0; mi1 = mt1;
                float rs0 = 0.f, rs1 = 0.f;
                #pragma unroll
                for (int nt = 0; nt < 8; nt++) {
                    s[nt][0] = exp2f(s[nt][0] - mt0); rs0 += s[nt][0];
                    s[nt][1] = exp2f(s[nt][1] - mt0); rs0 += s[nt][1];
                    s[nt][2] = exp2f(s[nt][2] - mt1); rs1 += s[nt][2];
                    s[nt][3] = exp2f(s[nt][3] - mt1); rs1 += s[nt][3];
                }
                rs0 += __shfl_xor_sync(0xFFFFFFFFu, rs0, 1);
                rs0 += __shfl_xor_sync(0xFFFFFFFFu, rs0, 2);
                rs1 += __shfl_xor_sync(0xFFFFFFFFu, rs1, 1);
                rs1 += __shfl_xor_sync(0xFFFFFFFFu, rs1, 2);
                li0 = li0 * al0 + rs0;
                li1 = li1 * al1 + rs1;
                #pragma unroll
                for (int nt = 0; nt < 8; nt++) {
                    o[nt][0] *= al0; o[nt][1] *= al0;
                    o[nt][2] *= al1; o[nt][3] *= al1;
                }

                #pragma unroll
                for (int t = 0; t < 4; t++) {
                    uint32_t pa[4];
                    pa[0] = pack_bf16(s[2 * t][0],     s[2 * t][1]);
                    pa[1] = pack_bf16(s[2 * t][2],     s[2 * t][3]);
                    pa[2] = pack_bf16(s[2 * t + 1][0], s[2 * t + 1][1]);
                    pa[3] = pack_bf16(s[2 * t + 1][2], s[2 * t + 1][3]);
                    #pragma unroll
                    for (int np = 0; np < 4; np++) {
                        uint32_t t0, t1, t2, t3;
                        ldsm4t(t0, t1, t2, t3,
                               sptr(Vs + (srow + t * 16 + vrow) * G_PITCHB + np * 32 + vhi));
                        mma16(o[np * 2], pa, t0, t1);
                        mma16(o[np * 2 + 1], pa, t2, t3);
                    }
                }
            }
        }

        const float inv0 = 1.f / li0, inv1 = 1.f / li1;
        const int r0 = q0 + warp * 16 + (lane >> 2);
        #pragma unroll
        for (int nt = 0; nt < 8; nt++) {
            int dc = nt * 8 + (lane & 3) * 2;
            uint32_t w0 = pack_bf16(o[nt][0] * inv0, o[nt][1] * inv0);
            uint32_t w1 = pack_bf16(o[nt][2] * inv1, o[nt][3] * inv1);
            *(uint32_t*)&g_ctx[(size_t)(batch * SEQ + r0) * D_MODEL + h * HD + dc] = w0;
            *(uint32_t*)&g_ctx[(size_t)(batch * SEQ + r0 + 8) * D_MODEL + h * HD + dc] = w1;
        }
    }
}

// ---------------------------------------------------------------------------
extern "C" void kernel_launch(void* const* d_in, const int* in_sizes, int n_in,
                              void* d_out, int out_size) {
    const float* x  = (const float*)d_in[0];
    const unsigned char* kpm = (const unsigned char*)d_in[1];
    const float* qw = (const float*)d_in[2];
    const float* kw = (const float*)d_in[3];
    const float* vw = (const float*)d_in[4];
    const float* ow = (const float*)d_in[5];
    const float* ob = (const float*)d_in[6];
    const float* lg = (const float*)d_in[7];
    const float* lb = (const float*)d_in[8];
    float* out = (float*)d_out;

    static bool attr_done = false;
    if (!attr_done) {
        cudaFuncSetAttribute(gemm_qkv, cudaFuncAttributeMaxDynamicSharedMemorySize, G_SMEM_BYTES);
        cudaFuncSetAttribute(gemm_out, cudaFuncAttributeMaxDynamicSharedMemorySize, G_SMEM_BYTES);
        cudaFuncSetAttribute(attn_kernel, cudaFuncAttributeMaxDynamicSharedMemorySize, A_SMEM_BYTES);
        attr_done = true;
    }

    prep_kernel<<<12800, 256>>>(qw, kw, vw, ow, x, lg, lb);
    gemm_qkv<<<dim3(24, 64), 256, G_SMEM_BYTES>>>();
    attn_kernel<<<dim3(8, 64), 256, A_SMEM_BYTES>>>(kpm);
    gemm_out<<<dim3(8, 64), 256, G_SMEM_BYTES>>>(ob, x, out);
}

// round 15
// speedup vs baseline: 1.1320x; 1.0056x over previous
#include <cuda_runtime.h>
#include <cuda_bf16.h>
#include <cstdint>
#include <math.h>

#define D_MODEL 1024
#define NHEAD   16
#define HD      64
#define SEQ     2048
#define BATCH   4
#define MTOT    (BATCH*SEQ)      // 8192
#define BHN     (BATCH*NHEAD)    // 64

static __device__ __nv_bfloat16 g_xln[MTOT * D_MODEL];
static __device__ __nv_bfloat16 g_q[BHN * SEQ * HD];
static __device__ __nv_bfloat16 g_k[BHN * SEQ * HD];
static __device__ __nv_bfloat16 g_v[BHN * SEQ * HD];
static __device__ __nv_bfloat16 g_ctx[MTOT * D_MODEL];
static __device__ __nv_bfloat16 g_wq[D_MODEL * D_MODEL];
static __device__ __nv_bfloat16 g_wk[D_MODEL * D_MODEL];
static __device__ __nv_bfloat16 g_wv[D_MODEL * D_MODEL];
static __device__ __nv_bfloat16 g_wo[D_MODEL * D_MODEL];
static __device__ float g_emb[SEQ * HD];

// GEMM smem: 3 stages x (A[128] + B[128]) rows of 72 bf16 (144B pitch)
#define G_PITCHB  144
#define G_ASIZE   (128 * G_PITCHB)          // 18432
#define G_STAGE_BYTES (2 * G_ASIZE)          // 36864
#define G_SMEM_BYTES  (3 * G_STAGE_BYTES)    // 110592
// attn smem: 3 stages x (K[128][72] + V[128][72]) + mask[2048] + flags[32]
#define A_KROWS   128
#define A_HALF    (A_KROWS * G_PITCHB)       // 18432
#define A_STAGE_BYTES (2 * A_HALF)           // 36864
#define A_MASK_OFF (3 * A_STAGE_BYTES)       // 110592
#define A_FLAG_OFF (A_MASK_OFF + 2048)       // 112640
#define A_SMEM_BYTES  (A_FLAG_OFF + 32)      // 112672

// ---------------------------------------------------------------------------
// helpers
// ---------------------------------------------------------------------------
__device__ __forceinline__ uint32_t sptr(const void* p) {
    return (uint32_t)__cvta_generic_to_shared(p);
}
__device__ __forceinline__ uint32_t pack_bf16(float lo, float hi) {
    uint32_t d;
    asm("cvt.rn.bf16x2.f32 %0, %1, %2;" : "=r"(d) : "f"(hi), "f"(lo));
    return d;
}
__device__ __forceinline__ void ldsm4(uint32_t& r0, uint32_t& r1, uint32_t& r2, uint32_t& r3,
                                      uint32_t addr) {
    asm volatile("ldmatrix.sync.aligned.m8n8.x4.shared.b16 {%0,%1,%2,%3}, [%4];"
                 : "=r"(r0), "=r"(r1), "=r"(r2), "=r"(r3) : "r"(addr));
}
__device__ __forceinline__ void ldsm4t(uint32_t& r0, uint32_t& r1, uint32_t& r2, uint32_t& r3,
                                       uint32_t addr) {
    asm volatile("ldmatrix.sync.aligned.m8n8.x4.trans.shared.b16 {%0,%1,%2,%3}, [%4];"
                 : "=r"(r0), "=r"(r1), "=r"(r2), "=r"(r3) : "r"(addr));
}
__device__ __forceinline__ void mma16(float* c, const uint32_t* a, uint32_t b0, uint32_t b1) {
    asm volatile("mma.sync.aligned.m16n8k16.row.col.f32.bf16.bf16.f32 "
                 "{%0,%1,%2,%3}, {%4,%5,%6,%7}, {%8,%9}, {%0,%1,%2,%3};"
                 : "+f"(c[0]), "+f"(c[1]), "+f"(c[2]), "+f"(c[3])
                 : "r"(a[0]), "r"(a[1]), "r"(a[2]), "r"(a[3]), "r"(b0), "r"(b1));
}
__device__ __forceinline__ void cpa16(uint32_t dst, const void* src) {
    asm volatile("cp.async.cg.shared.global [%0], [%1], 16;" :: "r"(dst), "l"(src));
}
__device__ __forceinline__ void cp_commit() { asm volatile("cp.async.commit_group;"); }
template<int N> __device__ __forceinline__ void cp_wait() {
    asm volatile("cp.async.wait_group %0;" :: "n"(N));
}

// ---------------------------------------------------------------------------
// prep kernel: wcvt (blocks 0..2047, 8 floats/thread), emb (2048..2559),
// ln (2560..10751)
// ---------------------------------------------------------------------------
__global__ __launch_bounds__(256) void prep_kernel(const float* __restrict__ qw,
                                                   const float* __restrict__ kw,
                                                   const float* __restrict__ vw,
                                                   const float* __restrict__ ow,
                                                   const float* __restrict__ x,
                                                   const float* __restrict__ gam,
                                                   const float* __restrict__ bet) {
    const int bx = blockIdx.x;
    if (bx < 2048) {
        const int which = bx >> 9;
        const int blk = bx & 511;
        const float* src = (which == 0) ? qw : (which == 1) ? kw : (which == 2) ? vw : ow;
        __nv_bfloat16* dst = (which == 0) ? g_wq : (which == 1) ? g_wk
                            : (which == 2) ? g_wv : g_wo;
        int i = (blk * 256 + threadIdx.x) * 8;
        float4 v0 = *(const float4*)(src + i);
        float4 v1 = *(const float4*)(src + i + 4);
        uint4 o;
        o.x = pack_bf16(v0.x, v0.y);
        o.y = pack_bf16(v0.z, v0.w);
        o.z = pack_bf16(v1.x, v1.y);
        o.w = pack_bf16(v1.z, v1.w);
        *(uint4*)(dst + i) = o;
        return;
    }
    if (bx < 2560) {
        int idx = (bx - 2048) * 256 + threadIdx.x;
        if (idx < SEQ * HD) {
            int s = idx / HD, d = idx % HD;
            int i = d & 31;
            double invf = exp(-((double)(2 * i) / 64.0) * log(10000.0));
            double ang = (double)s * invf;
            g_emb[idx] = (float)((d < 32) ? sin(ang) : cos(ang));
        }
        return;
    }
    int row = bx - 2560;
    const float4* xr = (const float4*)(x + (size_t)row * D_MODEL);
    float4 v = xr[threadIdx.x];
    float sum = v.x + v.y + v.z + v.w;
    float sq  = v.x*v.x + v.y*v.y + v.z*v.z + v.w*v.w;
    #pragma unroll
    for (int o = 16; o; o >>= 1) {
        sum += __shfl_xor_sync(0xFFFFFFFFu, sum, o);
        sq  += __shfl_xor_sync(0xFFFFFFFFu, sq, o);
    }
    __shared__ float ssum[8], ssq[8];
    int w = threadIdx.x >> 5, l = threadIdx.x & 31;
    if (!l) { ssum[w] = sum; ssq[w] = sq; }
    __syncthreads();
    if (w == 0) {
        sum = (l < 8) ? ssum[l] : 0.f;
        sq  = (l < 8) ? ssq[l]  : 0.f;
        #pragma unroll
        for (int o = 4; o; o >>= 1) {
            sum += __shfl_xor_sync(0xFFFFFFFFu, sum, o);
            sq  += __shfl_xor_sync(0xFFFFFFFFu, sq, o);
        }
        if (!l) { ssum[0] = sum; ssq[0] = sq; }
    }
    __syncthreads();
    float mu  = ssum[0] * (1.f / D_MODEL);
    float var = ssq[0] * (1.f / D_MODEL) - mu * mu;
    float rs  = rsqrtf(var + 1e-5f);
    int c = threadIdx.x * 4;
    float4 g4 = *(const float4*)(gam + c);
    float4 b4 = *(const float4*)(bet + c);
    uint2 o;
    o.x = pack_bf16((v.x - mu) * rs * g4.x + b4.x, (v.y - mu) * rs * g4.y + b4.y);
    o.y = pack_bf16((v.z - mu) * rs * g4.z + b4.z, (v.w - mu) * rs * g4.w + b4.w);
    *(uint2*)(g_xln + (size_t)row * D_MODEL + c) = o;
}

// ---------------------------------------------------------------------------
// bf16 GEMM core (R10 config): CTA 128x128, k-stage 64 (16 iters), 3-stage ring.
// ---------------------------------------------------------------------------
struct GemmAcc { float a[4][4][4]; };

__device__ __forceinline__ void gemm_core(const __nv_bfloat16* __restrict__ A,
                                          const __nv_bfloat16* __restrict__ B,
                                          int m0, int n0, GemmAcc& G, char* sm) {
    const int tid  = threadIdx.x;
    const int lane = tid & 31, warp = tid >> 5;
    const int wm = warp >> 2, wn = warp & 3;

    #pragma unroll
    for (int mt = 0; mt < 4; mt++)
        #pragma unroll
        for (int nt = 0; nt < 4; nt++)
            #pragma unroll
            for (int j = 0; j < 4; j++) G.a[mt][nt][j] = 0.f;

    auto issue = [&](int st, int k0) {
        char* As = sm + st * G_STAGE_BYTES;
        char* Bs = As + G_ASIZE;
        #pragma unroll
        for (int t = 0; t < 4; t++) {
            int idx = tid + t * 256;
            int row = idx >> 3;
            int cb  = (idx & 7) * 16;
            cpa16(sptr(As + row * G_PITCHB + cb),
                  (const char*)(A + (size_t)(m0 + row) * D_MODEL + k0) + cb);
            cpa16(sptr(Bs + row * G_PITCHB + cb),
                  (const char*)(B + (size_t)(n0 + row) * D_MODEL + k0) + cb);
        }
        cp_commit();
    };

    issue(0, 0);
    issue(1, 64);

    const int arow = (lane & 15);
    const int ahi  = (lane >> 4) * 16;
    const int brow = ((lane >> 4) & 1) * 8 + (lane & 7);
    const int bhi  = ((lane >> 3) & 1) * 16;

    for (int kt = 0; kt < 16; kt++) {
        const int st = kt - (kt / 3) * 3;
        if (kt < 15) cp_wait<1>(); else cp_wait<0>();
        __syncthreads();
        if (kt + 2 < 16) issue((kt + 2) - ((kt + 2) / 3) * 3, (kt + 2) * 64);

        char* As = sm + st * G_STAGE_BYTES;
        char* Bs = As + G_ASIZE;
        #pragma unroll
        for (int ks = 0; ks < 4; ks++) {
            const int kkB = ks * 32;
            uint32_t af[4][4];
            #pragma unroll
            for (int mt = 0; mt < 4; mt++)
                ldsm4(af[mt][0], af[mt][1], af[mt][2], af[mt][3],
                      sptr(As + (wm * 64 + mt * 16 + arow) * G_PITCHB + kkB + ahi));
            uint32_t bf[4][2];
            #pragma unroll
            for (int np = 0; np < 2; np++) {
                uint32_t t0, t1, t2, t3;
                ldsm4(t0, t1, t2, t3,
                      sptr(Bs + (wn * 32 + np * 16 + brow) * G_PITCHB + kkB + bhi));
                bf[np * 2][0] = t0;     bf[np * 2][1] = t1;
                bf[np * 2 + 1][0] = t2; bf[np * 2 + 1][1] = t3;
            }
            #pragma unroll
            for (int mt = 0; mt < 4; mt++)
                #pragma unroll
                for (int nt = 0; nt < 4; nt++)
                    mma16(G.a[mt][nt], af[mt], bf[nt][0], bf[nt][1]);
        }
    }
}

// ---------------------------------------------------------------------------
// QKV proj: grid (24, 64). Fused rotary + q scale (0.125*log2e) + head-split.
// ---------------------------------------------------------------------------
__global__ __launch_bounds__(256, 2) void gemm_qkv() {
    extern __shared__ char dynsm_g[];
    const int m0 = blockIdx.y * 128;
    const int which = blockIdx.x >> 3;
    const int n0 = (blockIdx.x & 7) * 128;
    const __nv_bfloat16* W = (which == 0) ? g_wq : (which == 1) ? g_wk : g_wv;

    GemmAcc G;
    gemm_core(g_xln, W, m0, n0, G, dynsm_g);

    const int lane = threadIdx.x & 31, warp = threadIdx.x >> 5;
    const int wm = warp >> 2, wn = warp & 3;
    __nv_bfloat16* dst = (which == 0) ? g_q : (which == 1) ? g_k : g_v;
    const float qscale = 0.125f * 1.4426950408889634f;

    #pragma unroll
    for (int mt = 0; mt < 4; mt++) {
        #pragma unroll
        for (int rh = 0; rh < 2; rh++) {
            int m = m0 + wm * 64 + mt * 16 + rh * 8 + (lane >> 2);
            int b = m >> 11, s = m & 2047;
            #pragma unroll
            for (int nt = 0; nt < 4; nt++) {
                int n  = n0 + wn * 32 + nt * 8 + (lane & 3) * 2;
                int h  = n >> 6, dc = n & 63;
                float ex = 1.f, ey = 1.f;
                if (which < 2) {
                    float2 e = *(const float2*)&g_emb[s * HD + dc];
                    ex = e.x; ey = e.y;
                    if (which == 0) { ex *= qscale; ey *= qscale; }
                }
                uint32_t o = pack_bf16(G.a[mt][nt][rh * 2 + 0] * ex,
                                       G.a[mt][nt][rh * 2 + 1] * ey);
                *(uint32_t*)&dst[((size_t)(b * NHEAD + h) * SEQ + s) * HD + dc] = o;
            }
        }
    }
}

// ---------------------------------------------------------------------------
// out proj + bias + residual (R10 config): grid (8, 64)
// ---------------------------------------------------------------------------
__global__ __launch_bounds__(256, 2) void gemm_out(const float* __restrict__ ob,
                                                   const float* __restrict__ x,
                                                   float* __restrict__ out) {
    extern __shared__ char dynsm_o[];
    const int m0 = blockIdx.y * 128;
    const int n0 = blockIdx.x * 128;

    GemmAcc G;
    gemm_core(g_ctx, g_wo, m0, n0, G, dynsm_o);

    const int lane = threadIdx.x & 31, warp = threadIdx.x >> 5;
    const int wm = warp >> 2, wn = warp & 3;

    #pragma unroll
    for (int mt = 0; mt < 4; mt++) {
        #pragma unroll
        for (int rh = 0; rh < 2; rh++) {
            int m = m0 + wm * 64 + mt * 16 + rh * 8 + (lane >> 2);
            #pragma unroll
            for (int nt = 0; nt < 4; nt++) {
                int n = n0 + wn * 32 + nt * 8 + (lane & 3) * 2;
                float2 bb = *(const float2*)&ob[n];
                float2 xx = *(const float2*)&x[(size_t)m * D_MODEL + n];
                float2 o;
                o.x = G.a[mt][nt][rh * 2 + 0] + bb.x + xx.x;
                o.y = G.a[mt][nt][rh * 2 + 1] + bb.y + xx.y;
                *(float2*)&out[(size_t)m * D_MODEL + n] = o;
            }
        }
    }
}

// ---------------------------------------------------------------------------
// Flash attention: R14 + deferred li reduction (per-thread partial sums,
// quad-reduced once in the epilogue).
// ---------------------------------------------------------------------------
__global__ __launch_bounds__(256, 2) void attn_kernel(const unsigned char* __restrict__ kpm) {
    extern __shared__ char dynsm_a[];

    const int tid = threadIdx.x, lane = tid & 31, warp = tid >> 5;
    const int bh = blockIdx.y;
    const int batch = bh >> 4, h = bh & 15;

    const __nv_bfloat16* __restrict__ Qg = g_q + (size_t)bh * SEQ * HD;
    const __nv_bfloat16* __restrict__ Kg = g_k + (size_t)bh * SEQ * HD;
    const __nv_bfloat16* __restrict__ Vg = g_v + (size_t)bh * SEQ * HD;
    const unsigned char* __restrict__ maskg = kpm + (size_t)batch * SEQ;
    unsigned char* smask = (unsigned char*)(dynsm_a + A_MASK_OFF);
    unsigned char* sflag = (unsigned char*)(dynsm_a + A_FLAG_OFF);

    auto stageK = [&](int st) { return dynsm_a + st * A_STAGE_BYTES; };
    auto stageV = [&](int st) { return dynsm_a + st * A_STAGE_BYTES + A_HALF; };

    auto issue = [&](int st, int kbase) {
        char* Ks = stageK(st);
        char* Vs = stageV(st);
        #pragma unroll
        for (int t = 0; t < 4; t++) {
            int idx = tid + t * 256;
            int row = idx >> 3;
            int cb  = (idx & 7) * 16;
            cpa16(sptr(Ks + row * G_PITCHB + cb),
                  (const char*)(Kg + (size_t)(kbase + row) * HD) + cb);
            cpa16(sptr(Vs + row * G_PITCHB + cb),
                  (const char*)(Vg + (size_t)(kbase + row) * HD) + cb);
        }
        cp_commit();
    };

    // stage full mask (2048 B), then per-64-key-block nonzero flags
    *(uint2*)(smask + tid * 8) = *(const uint2*)(maskg + tid * 8);
    __syncthreads();
    if (tid < 32) {
        const uint32_t* mw = (const uint32_t*)(smask + tid * 64);
        uint32_t acc = 0;
        #pragma unroll
        for (int i = 0; i < 16; i++) acc |= mw[i];
        sflag[tid] = acc ? 1 : 0;
    }

    const int brow = ((lane >> 4) & 1) * 8 + (lane & 7);
    const int bhi  = ((lane >> 3) & 1) * 16;
    const int vrow = ((lane >> 3) & 1) * 8 + (lane & 7);
    const int vhi  = (lane >> 4) * 16;

    #pragma unroll 1
    for (int ph = 0; ph < 2; ph++) {
        const int qb = ph ? (15 - blockIdx.x) : blockIdx.x;
        const int q0 = qb * 128;
        const int nkb = qb + 1;

        __syncthreads();          // ring reuse + flag visibility
        issue(0, 0);
        if (nkb > 1) issue(1, 128);

        uint32_t qf[4][4];
        {
            const int r0 = q0 + warp * 16 + (lane >> 2);
            #pragma unroll
            for (int t = 0; t < 4; t++) {
                int c = t * 16 + (lane & 3) * 2;
                qf[t][0] = *(const uint32_t*)&Qg[(size_t)r0 * HD + c];
                qf[t][1] = *(const uint32_t*)&Qg[(size_t)(r0 + 8) * HD + c];
                qf[t][2] = *(const uint32_t*)&Qg[(size_t)r0 * HD + c + 8];
                qf[t][3] = *(const uint32_t*)&Qg[(size_t)(r0 + 8) * HD + c + 8];
            }
        }

        float o[8][4];
        #pragma unroll
        for (int nt = 0; nt < 8; nt++)
            #pragma unroll
            for (int j = 0; j < 4; j++) o[nt][j] = 0.f;
        float mi0 = -1e30f, mi1 = -1e30f, li0 = 0.f, li1 = 0.f;

        #pragma unroll 1
        for (int kb = 0; kb < nkb; kb++) {
            const int st = kb - (kb / 3) * 3;
            if (kb + 1 < nkb) cp_wait<1>(); else cp_wait<0>();
            __syncthreads();
            if (kb + 2 < nkb) issue((kb + 2) - ((kb + 2) / 3) * 3, (kb + 2) * 128);

            const char* Ks = stageK(st);
            const char* Vs = stageV(st);

            #pragma unroll 1
            for (int sub = 0; sub < 2; sub++) {
                const int kbase = kb * 128 + sub * 64;
                const int srow  = sub * 64;
                const bool active = (kbase <= q0 + warp * 16 + 15);
                if (!active) continue;

                float s[8][4];
                #pragma unroll
                for (int nt = 0; nt < 8; nt++)
                    #pragma unroll
                    for (int j = 0; j < 4; j++) s[nt][j] = 0.f;
                #pragma unroll
                for (int ks = 0; ks < 4; ks++) {
                    #pragma unroll
                    for (int np = 0; np < 4; np++) {
                        uint32_t t0, t1, t2, t3;
                        ldsm4(t0, t1, t2, t3,
                              sptr(Ks + (srow + np * 16 + brow) * G_PITCHB + ks * 32 + bhi));
                        mma16(s[np * 2], qf[ks], t0, t1);
                        mma16(s[np * 2 + 1], qf[ks], t2, t3);
                    }
                }

                // padding mask: only when this 64-key block has any masked keys
                if (sflag[kbase >> 6]) {
                    #pragma unroll
                    for (int nt = 0; nt < 8; nt++) {
                        int c = nt * 8 + (lane & 3) * 2;
                        unsigned char mb0 = smask[kbase + c], mb1 = smask[kbase + c + 1];
                        if (mb0) { s[nt][0] = -INFINITY; s[nt][2] = -INFINITY; }
                        if (mb1) { s[nt][1] = -INFINITY; s[nt][3] = -INFINITY; }
                    }
                }
                // causal mask (diagonal block only)
                const int row0 = q0 + warp * 16 + (lane >> 2);
                if ((kbase + 63) > (q0 + warp * 16)) {
                    #pragma unroll
                    for (int nt = 0; nt < 8; nt++) {
                        int cg = kbase + nt * 8 + (lane & 3) * 2;
                        if (cg     > row0)     s[nt][0] = -INFINITY;
                        if (cg + 1 > row0)     s[nt][1] = -INFINITY;
                        if (cg     > row0 + 8) s[nt][2] = -INFINITY;
                        if (cg + 1 > row0 + 8) s[nt][3] = -INFINITY;
                    }
                }

                float mx0 = -1e30f, mx1 = -1e30f;
                #pragma unroll
                for (int nt = 0; nt < 8; nt++) {
                    mx0 = fmaxf(mx0, fmaxf(s[nt][0], s[nt][1]));
                    mx1 = fmaxf(mx1, fmaxf(s[nt][2], s[nt][3]));
                }
                mx0 = fmaxf(mx0, __shfl_xor_sync(0xFFFFFFFFu, mx0, 1));
                mx0 = fmaxf(mx0, __shfl_xor_sync(0xFFFFFFFFu, mx0, 2));
                mx1 = fmaxf(mx1, __shfl_xor_sync(0xFFFFFFFFu, mx1, 1));
                mx1 = fmaxf(mx1, __shfl_xor_sync(0xFFFFFFFFu, mx1, 2));
                float mt0 = fmaxf(mi0, mx0), mt1 = fmaxf(mi1, mx1);
                float al0 = exp2f(mi0 - mt0), al1 = exp2f(mi1 - mt1);
                mi0 = mt0; mi1 = mt1;
                // per-thread partial row sums (quad-reduced once at the end)
                float rs0 = 0.f, rs1 = 0.f;
                #pragma unroll
                for (int nt = 0; nt < 8; nt++) {
                    s[nt][0] = exp2f(s[nt][0] - mt0); rs0 += s[nt][0];
                    s[nt][1] = exp2f(s[nt][1] - mt0); rs0 += s[nt][1];
                    s[nt][2] = exp2f(s[nt][2] - mt1); rs1 += s[nt][2];
                    s[nt][3] = exp2f(s[nt][3] - mt1); rs1 += s[nt][3];
                }
                li0 = li0 * al0 + rs0;
                li1 = li1 * al1 + rs1;
                #pragma unroll
                for (int nt = 0; nt < 8; nt++) {
                    o[nt][0] *= al0; o[nt][1] *= al0;
                    o[nt][2] *= al1; o[nt][3] *= al1;
                }

                #pragma unroll
                for (int t = 0; t < 4; t++) {
                    uint32_t pa[4];
                    pa[0] = pack_bf16(s[2 * t][0],     s[2 * t][1]);
                    pa[1] = pack_bf16(s[2 * t][2],     s[2 * t][3]);
                    pa[2] = pack_bf16(s[2 * t + 1][0], s[2 * t + 1][1]);
                    pa[3] = pack_bf16(s[2 * t + 1][2], s[2 * t + 1][3]);
                    #pragma unroll
                    for (int np = 0; np < 4; np++) {
                        uint32_t t0, t1, t2, t3;
                        ldsm4t(t0, t1, t2, t3,
                               sptr(Vs + (srow + t * 16 + vrow) * G_PITCHB + np * 32 + vhi));
                        mma16(o[np * 2], pa, t0, t1);
                        mma16(o[np * 2 + 1], pa, t2, t3);
                    }
                }
            }
        }

        // final quad reduction of per-thread partial sums
        li0 += __shfl_xor_sync(0xFFFFFFFFu, li0, 1);
        li0 += __shfl_xor_sync(0xFFFFFFFFu, li0, 2);
        li1 += __shfl_xor_sync(0xFFFFFFFFu, li1, 1);
        li1 += __shfl_xor_sync(0xFFFFFFFFu, li1, 2);

        const float inv0 = 1.f / li0, inv1 = 1.f / li1;
        const int r0 = q0 + warp * 16 + (lane >> 2);
        #pragma unroll
        for (int nt = 0; nt < 8; nt++) {
            int dc = nt * 8 + (lane & 3) * 2;
            uint32_t w0 = pack_bf16(o[nt][0] * inv0, o[nt][1] * inv0);
            uint32_t w1 = pack_bf16(o[nt][2] * inv1, o[nt][3] * inv1);
            *(uint32_t*)&g_ctx[(size_t)(batch * SEQ + r0) * D_MODEL + h * HD + dc] = w0;
            *(uint32_t*)&g_ctx[(size_t)(batch * SEQ + r0 + 8) * D_MODEL + h * HD + dc] = w1;
        }
    }
}

// ---------------------------------------------------------------------------
extern "C" void kernel_launch(void* const* d_in, const int* in_sizes, int n_in,
                              void* d_out, int out_size) {
    const float* x  = (const float*)d_in[0];
    const unsigned char* kpm = (const unsigned char*)d_in[1];
    const float* qw = (const float*)d_in[2];
    const float* kw = (const float*)d_in[3];
    const float* vw = (const float*)d_in[4];
    const float* ow = (const float*)d_in[5];
    const float* ob = (const float*)d_in[6];
    const float* lg = (const float*)d_in[7];
    const float* lb = (const float*)d_in[8];
    float* out = (float*)d_out;

    static bool attr_done = false;
    if (!attr_done) {
        cudaFuncSetAttribute(gemm_qkv, cudaFuncAttributeMaxDynamicSharedMemorySize, G_SMEM_BYTES);
        cudaFuncSetAttribute(gemm_out, cudaFuncAttributeMaxDynamicSharedMemorySize, G_SMEM_BYTES);
        cudaFuncSetAttribute(attn_kernel, cudaFuncAttributeMaxDynamicSharedMemorySize, A_SMEM_BYTES);
        attr_done = true;
    }

    prep_kernel<<<10752, 256>>>(qw, kw, vw, ow, x, lg, lb);
    gemm_qkv<<<dim3(24, 64), 256, G_SMEM_BYTES>>>();
    attn_kernel<<<dim3(8, 64), 256, A_SMEM_BYTES>>>(kpm);
    gemm_out<<<dim3(8, 64), 256, G_SMEM_BYTES>>>(ob, x, out);
}